// round 8
// baseline (speedup 1.0000x reference)
#include <cuda_runtime.h>

// 24-qubit state-vector sim, 8 two-qubit gates, step s -> qubits (s, s+7).
// Two passes of 4 gates; gates fused in PAIRS in registers (16-amp supergroup
// per thread). R8 = R7 champion +:
//  - weights packed naturally (wr,wi): 16 u64 = 32 regs (was 64 duplicated),
//    two-accumulator complex MAC with one ADD2 combine per output.
//  - A-accumulators computed first (only P=(sr,sr) dups live), then Q/B phase:
//    peak live ~75 regs -> __launch_bounds__(256,3) = 3 CTAs/SM (occ 23->34%).
// Swizzle SWZ(x) = x ^ x4*0b0101 ^ x5*0b1010 is conflict-free at 16-lane
// phase granularity for every access pattern (verified GF(2) rank-4).

#define NSTATE (1u << 24)
typedef unsigned long long u64;

__device__ __forceinline__ u64 pk2(float lo, float hi) {
    u64 r; asm("mov.b64 %0, {%1, %2};" : "=l"(r) : "f"(lo), "f"(hi)); return r;
}
__device__ __forceinline__ void upk2(u64 v, float& lo, float& hi) {
    asm("mov.b64 {%0, %1}, %2;" : "=f"(lo), "=f"(hi) : "l"(v));
}
__device__ __forceinline__ u64 ffma2(u64 a, u64 b, u64 c) {
    u64 d; asm("fma.rn.f32x2 %0, %1, %2, %3;" : "=l"(d) : "l"(a), "l"(b), "l"(c)); return d;
}
__device__ __forceinline__ u64 fmul2(u64 a, u64 b) {
    u64 d; asm("mul.rn.f32x2 %0, %1, %2;" : "=l"(d) : "l"(a), "l"(b)); return d;
}
__device__ __forceinline__ u64 fadd2(u64 a, u64 b) {
    u64 d; asm("add.rn.f32x2 %0, %1, %2;" : "=l"(d) : "l"(a), "l"(b)); return d;
}
__device__ __forceinline__ float negf(float v) {
    return __int_as_float(__float_as_int(v) ^ 0x80000000u);
}
// Phase-granularity conflict-free swizzle: fold bit4 -> {0,2}, bit5 -> {1,3}.
__device__ __forceinline__ unsigned SWZ(unsigned x) {
    return x ^ (((x >> 4) & 1u) * 5u) ^ (((x >> 5) & 1u) * 10u);
}

// Complex 4x4 gate on a quad of packed (re,im) amps, weights packed (wr,wi).
// A_g = sum_h (sr,sr)*(wr,wi);  B_g = sum_h (si,si)*(wr,wi);
// out_g = A_g + (-B.hi, B.lo).  9 fma-pipe ops per output.
__device__ __forceinline__ void gate4(u64& v0, u64& v1, u64& v2, u64& v3,
                                      const u64* __restrict__ w)
{
    float r0,i0,r1,i1,r2,i2,r3,i3;
    upk2(v0,r0,i0); upk2(v1,r1,i1); upk2(v2,r2,i2); upk2(v3,r3,i3);

    // Phase 1: real-part duplicates only.
    u64 P0 = pk2(r0, r0), P1 = pk2(r1, r1), P2 = pk2(r2, r2), P3 = pk2(r3, r3);
    u64 A0 = fmul2(P0, w[0]);
    A0 = ffma2(P1, w[1], A0); A0 = ffma2(P2, w[2], A0); A0 = ffma2(P3, w[3], A0);
    u64 A1 = fmul2(P0, w[4]);
    A1 = ffma2(P1, w[5], A1); A1 = ffma2(P2, w[6], A1); A1 = ffma2(P3, w[7], A1);
    u64 A2 = fmul2(P0, w[8]);
    A2 = ffma2(P1, w[9], A2); A2 = ffma2(P2, w[10], A2); A2 = ffma2(P3, w[11], A2);
    u64 A3 = fmul2(P0, w[12]);
    A3 = ffma2(P1, w[13], A3); A3 = ffma2(P2, w[14], A3); A3 = ffma2(P3, w[15], A3);

    // Phase 2: imag-part duplicates (P regs dead, reuse).
    u64 Q0 = pk2(i0, i0), Q1 = pk2(i1, i1), Q2 = pk2(i2, i2), Q3 = pk2(i3, i3);
    {
        u64 B = fmul2(Q0, w[0]);
        B = ffma2(Q1, w[1], B); B = ffma2(Q2, w[2], B); B = ffma2(Q3, w[3], B);
        float bl, bh; upk2(B, bl, bh);
        v0 = fadd2(A0, pk2(negf(bh), bl));
    }
    {
        u64 B = fmul2(Q0, w[4]);
        B = ffma2(Q1, w[5], B); B = ffma2(Q2, w[6], B); B = ffma2(Q3, w[7], B);
        float bl, bh; upk2(B, bl, bh);
        v1 = fadd2(A1, pk2(negf(bh), bl));
    }
    {
        u64 B = fmul2(Q0, w[8]);
        B = ffma2(Q1, w[9], B); B = ffma2(Q2, w[10], B); B = ffma2(Q3, w[11], B);
        float bl, bh; upk2(B, bl, bh);
        v2 = fadd2(A2, pk2(negf(bh), bl));
    }
    {
        u64 B = fmul2(Q0, w[12]);
        B = ffma2(Q1, w[13], B); B = ffma2(Q2, w[14], B); B = ffma2(Q3, w[15], B);
        float bl, bh; upk2(B, bl, bh);
        v3 = fadd2(A3, pk2(negf(bh), bl));
    }
}

// Two fused gate steps on a 16-amp supergroup. P0..P3 = inserted tile-bit
// positions (ascending). First gate varies group bits (0,2)=(P0,P2);
// second gate varies (1,3)=(P1,P3). All amp-array indices literal.
template <int P0, int P1, int P2, int P3>
__device__ __forceinline__ void apply_pair(float2* sm, unsigned tid,
                                           const float* __restrict__ gp0,
                                           const float* __restrict__ gp1)
{
    unsigned x = tid;
    x = ((x & ~((1u << P0) - 1u)) << 1) | (x & ((1u << P0) - 1u));
    x = ((x & ~((1u << P1) - 1u)) << 1) | (x & ((1u << P1) - 1u));
    x = ((x & ~((1u << P2) - 1u)) << 1) | (x & ((1u << P2) - 1u));
    x = ((x & ~((1u << P3) - 1u)) << 1) | (x & ((1u << P3) - 1u));

    u64 p[16];
    #pragma unroll
    for (int i = 0; i < 16; ++i) {
        unsigned off = ((i & 1)        ? (1u << P0) : 0u)
                     | (((i >> 1) & 1) ? (1u << P1) : 0u)
                     | (((i >> 2) & 1) ? (1u << P2) : 0u)
                     | (((i >> 3) & 1) ? (1u << P3) : 0u);
        float2 v = sm[SWZ(x | off)];
        p[i] = pk2(v.x, v.y);
    }

    {   // gate 0: vary (bit0,bit2) -> quads {0,1,4,5},{2,3,6,7},{8..},{10..}
        u64 w[16];
        #pragma unroll
        for (int k = 0; k < 16; ++k)
            w[k] = pk2(__ldg(gp0 + k), __ldg(gp0 + 16 + k));
        gate4(p[0],  p[1],  p[4],  p[5],  w);
        gate4(p[2],  p[3],  p[6],  p[7],  w);
        gate4(p[8],  p[9],  p[12], p[13], w);
        gate4(p[10], p[11], p[14], p[15], w);
    }
    {   // gate 1: vary (bit1,bit3) -> quads {0,2,8,10},{1,3,9,11},...
        u64 w[16];
        #pragma unroll
        for (int k = 0; k < 16; ++k)
            w[k] = pk2(__ldg(gp1 + k), __ldg(gp1 + 16 + k));
        gate4(p[0], p[2], p[8],  p[10], w);
        gate4(p[1], p[3], p[9],  p[11], w);
        gate4(p[4], p[6], p[12], p[14], w);
        gate4(p[5], p[7], p[13], p[15], w);
    }

    #pragma unroll
    for (int i = 0; i < 16; ++i) {
        unsigned off = ((i & 1)        ? (1u << P0) : 0u)
                     | (((i >> 1) & 1) ? (1u << P1) : 0u)
                     | (((i >> 2) & 1) ? (1u << P2) : 0u)
                     | (((i >> 3) & 1) ? (1u << P3) : 0u);
        float lo, hi; upk2(p[i], lo, hi);
        sm[SWZ(x | off)] = make_float2(lo, hi);
    }
}

template <int PASS>
__global__ __launch_bounds__(256, 3)
void qsim_pass(const float* __restrict__ in, float* __restrict__ out,
               const float* __restrict__ gates)
{
    __shared__ float2 sm[4096];
    const unsigned tid = threadIdx.x;
    const unsigned b = blockIdx.x;
    const unsigned hi = (PASS == 0) ? (b << 12)
                                    : (((b & 7u) << 8) | ((b >> 3) << 15));

    // ---- Stage tile: LDG.128 per plane, conflict-free STS.64 ----
    #pragma unroll
    for (int j = 0; j < 4; ++j) {
        unsigned a = (tid + 256u * j) * 4u;
        unsigned g = (PASS == 0) ? (hi | a)
                                 : (hi | ((a >> 8) << 11) | (a & 255u));
        float4 r4 = *(const float4*)(in + g);
        float4 m4 = *(const float4*)(in + NSTATE + g);
        sm[SWZ(a + 0)] = make_float2(r4.x, m4.x);
        sm[SWZ(a + 1)] = make_float2(r4.y, m4.y);
        sm[SWZ(a + 2)] = make_float2(r4.z, m4.z);
        sm[SWZ(a + 3)] = make_float2(r4.w, m4.w);
    }
    __syncthreads();

    // ---- Two fused gate pairs ----
    if (PASS == 0) apply_pair<0, 1, 7, 8>(sm, tid, gates + 0 * 32, gates + 1 * 32);
    else           apply_pair<4, 5, 8, 9>(sm, tid, gates + 4 * 32, gates + 5 * 32);
    __syncthreads();
    if (PASS == 0) apply_pair<2, 3, 9, 10>(sm, tid, gates + 2 * 32, gates + 3 * 32);
    else           apply_pair<6, 7, 10, 11>(sm, tid, gates + 6 * 32, gates + 7 * 32);
    __syncthreads();

    // ---- Write back: STG.128 per plane ----
    #pragma unroll
    for (int j = 0; j < 4; ++j) {
        unsigned a = (tid + 256u * j) * 4u;
        unsigned g = (PASS == 0) ? (hi | a)
                                 : (hi | ((a >> 8) << 11) | (a & 255u));
        float2 v0 = sm[SWZ(a + 0)], v1 = sm[SWZ(a + 1)];
        float2 v2 = sm[SWZ(a + 2)], v3 = sm[SWZ(a + 3)];
        *(float4*)(out + g)          = make_float4(v0.x, v1.x, v2.x, v3.x);
        *(float4*)(out + NSTATE + g) = make_float4(v0.y, v1.y, v2.y, v3.y);
    }
}

extern "C" void kernel_launch(void* const* d_in, const int* in_sizes, int n_in,
                              void* d_out, int out_size)
{
    const float* state = (const float*)d_in[0];   // 2 * 2^24 floats (re, im planes)
    const float* gates = (const float*)d_in[1];   // 8 * 2 * 4 * 4 floats
    float* out = (float*)d_out;

    qsim_pass<0><<<4096, 256>>>(state, out, gates);   // steps 0..3
    qsim_pass<1><<<4096, 256>>>(out, out, gates);     // steps 4..7 (in place, disjoint)
}

// round 9
// speedup vs baseline: 1.1286x; 1.1286x over previous
#include <cuda_runtime.h>

// 24-qubit state-vector sim, 8 two-qubit gates, step s -> qubits (s, s+7).
// Two passes of 4 gates, fused in register PAIRS (16-amp supergroup/thread).
// R9 = R7 structure + R8 low-register math (weights packed (wr,wi), two-phase
// A/B accumulation, ~88 live regs) + __launch_bounds__(128,5):
//   cap 102 regs (fits, unlike R8's 84 -> spills), 5 CTAs/SM = 20 warps.
// Tiles are 2048 amps (128 threads x 16):
//   pass0 tile = amp bits 0..10; pass1 tile = bits {0,1,2}U{4..7}U{11..14}.
// SWZ (fold bit4->{0,2}, bit5->{1,3}) verified conflict-free at 16-lane phase
// granularity for every access pattern of both passes.

#define NSTATE (1u << 24)
typedef unsigned long long u64;

__device__ __forceinline__ u64 pk2(float lo, float hi) {
    u64 r; asm("mov.b64 %0, {%1, %2};" : "=l"(r) : "f"(lo), "f"(hi)); return r;
}
__device__ __forceinline__ void upk2(u64 v, float& lo, float& hi) {
    asm("mov.b64 {%0, %1}, %2;" : "=f"(lo), "=f"(hi) : "l"(v));
}
__device__ __forceinline__ u64 ffma2(u64 a, u64 b, u64 c) {
    u64 d; asm("fma.rn.f32x2 %0, %1, %2, %3;" : "=l"(d) : "l"(a), "l"(b), "l"(c)); return d;
}
__device__ __forceinline__ u64 fmul2(u64 a, u64 b) {
    u64 d; asm("mul.rn.f32x2 %0, %1, %2;" : "=l"(d) : "l"(a), "l"(b)); return d;
}
__device__ __forceinline__ u64 fadd2(u64 a, u64 b) {
    u64 d; asm("add.rn.f32x2 %0, %1, %2;" : "=l"(d) : "l"(a), "l"(b)); return d;
}
__device__ __forceinline__ float negf(float v) {
    return __int_as_float(__float_as_int(v) ^ 0x80000000u);
}
__device__ __forceinline__ unsigned SWZ(unsigned x) {
    return x ^ (((x >> 4) & 1u) * 5u) ^ (((x >> 5) & 1u) * 10u);
}

// Complex 4x4 gate on a quad; weights packed (wr,wi).
// A_g = sum_h (sr_h,sr_h)*(wr,wi); B_g = sum_h (si_h,si_h)*(wr,wi);
// out_g = A_g + (-B_g.hi, B_g.lo).
__device__ __forceinline__ void gate4(u64& v0, u64& v1, u64& v2, u64& v3,
                                      const u64* __restrict__ w)
{
    float r0,i0,r1,i1,r2,i2,r3,i3;
    upk2(v0,r0,i0); upk2(v1,r1,i1); upk2(v2,r2,i2); upk2(v3,r3,i3);

    u64 P0 = pk2(r0, r0), P1 = pk2(r1, r1), P2 = pk2(r2, r2), P3 = pk2(r3, r3);
    u64 A0 = fmul2(P0, w[0]);
    A0 = ffma2(P1, w[1], A0); A0 = ffma2(P2, w[2], A0); A0 = ffma2(P3, w[3], A0);
    u64 A1 = fmul2(P0, w[4]);
    A1 = ffma2(P1, w[5], A1); A1 = ffma2(P2, w[6], A1); A1 = ffma2(P3, w[7], A1);
    u64 A2 = fmul2(P0, w[8]);
    A2 = ffma2(P1, w[9], A2); A2 = ffma2(P2, w[10], A2); A2 = ffma2(P3, w[11], A2);
    u64 A3 = fmul2(P0, w[12]);
    A3 = ffma2(P1, w[13], A3); A3 = ffma2(P2, w[14], A3); A3 = ffma2(P3, w[15], A3);

    u64 Q0 = pk2(i0, i0), Q1 = pk2(i1, i1), Q2 = pk2(i2, i2), Q3 = pk2(i3, i3);
    {
        u64 B = fmul2(Q0, w[0]);
        B = ffma2(Q1, w[1], B); B = ffma2(Q2, w[2], B); B = ffma2(Q3, w[3], B);
        float bl, bh; upk2(B, bl, bh);
        v0 = fadd2(A0, pk2(negf(bh), bl));
    }
    {
        u64 B = fmul2(Q0, w[4]);
        B = ffma2(Q1, w[5], B); B = ffma2(Q2, w[6], B); B = ffma2(Q3, w[7], B);
        float bl, bh; upk2(B, bl, bh);
        v1 = fadd2(A1, pk2(negf(bh), bl));
    }
    {
        u64 B = fmul2(Q0, w[8]);
        B = ffma2(Q1, w[9], B); B = ffma2(Q2, w[10], B); B = ffma2(Q3, w[11], B);
        float bl, bh; upk2(B, bl, bh);
        v2 = fadd2(A2, pk2(negf(bh), bl));
    }
    {
        u64 B = fmul2(Q0, w[12]);
        B = ffma2(Q1, w[13], B); B = ffma2(Q2, w[14], B); B = ffma2(Q3, w[15], B);
        float bl, bh; upk2(B, bl, bh);
        v3 = fadd2(A3, pk2(negf(bh), bl));
    }
}

// Two fused gate steps on a 16-amp supergroup; tid is 7 bits (128 threads).
// First gate varies group bits (0,2)=(P0,P2); second varies (1,3)=(P1,P3).
template <int P0, int P1, int P2, int P3>
__device__ __forceinline__ void apply_pair(float2* sm, unsigned tid,
                                           const float* __restrict__ gp0,
                                           const float* __restrict__ gp1)
{
    unsigned x = tid;
    x = ((x & ~((1u << P0) - 1u)) << 1) | (x & ((1u << P0) - 1u));
    x = ((x & ~((1u << P1) - 1u)) << 1) | (x & ((1u << P1) - 1u));
    x = ((x & ~((1u << P2) - 1u)) << 1) | (x & ((1u << P2) - 1u));
    x = ((x & ~((1u << P3) - 1u)) << 1) | (x & ((1u << P3) - 1u));

    u64 p[16];
    #pragma unroll
    for (int i = 0; i < 16; ++i) {
        unsigned off = ((i & 1)        ? (1u << P0) : 0u)
                     | (((i >> 1) & 1) ? (1u << P1) : 0u)
                     | (((i >> 2) & 1) ? (1u << P2) : 0u)
                     | (((i >> 3) & 1) ? (1u << P3) : 0u);
        float2 v = sm[SWZ(x | off)];
        p[i] = pk2(v.x, v.y);
    }

    {   // gate 0: vary (bit0,bit2)
        u64 w[16];
        #pragma unroll
        for (int k = 0; k < 16; ++k)
            w[k] = pk2(__ldg(gp0 + k), __ldg(gp0 + 16 + k));
        gate4(p[0],  p[1],  p[4],  p[5],  w);
        gate4(p[2],  p[3],  p[6],  p[7],  w);
        gate4(p[8],  p[9],  p[12], p[13], w);
        gate4(p[10], p[11], p[14], p[15], w);
    }
    {   // gate 1: vary (bit1,bit3)
        u64 w[16];
        #pragma unroll
        for (int k = 0; k < 16; ++k)
            w[k] = pk2(__ldg(gp1 + k), __ldg(gp1 + 16 + k));
        gate4(p[0], p[2], p[8],  p[10], w);
        gate4(p[1], p[3], p[9],  p[11], w);
        gate4(p[4], p[6], p[12], p[14], w);
        gate4(p[5], p[7], p[13], p[15], w);
    }

    #pragma unroll
    for (int i = 0; i < 16; ++i) {
        unsigned off = ((i & 1)        ? (1u << P0) : 0u)
                     | (((i >> 1) & 1) ? (1u << P1) : 0u)
                     | (((i >> 2) & 1) ? (1u << P2) : 0u)
                     | (((i >> 3) & 1) ? (1u << P3) : 0u);
        float lo, hi; upk2(p[i], lo, hi);
        sm[SWZ(x | off)] = make_float2(lo, hi);
    }
}

// Tile index (11 bits) -> global amp index.
template <int PASS>
__device__ __forceinline__ unsigned gmap(unsigned hi, unsigned a) {
    if (PASS == 0) return hi | a;                          // tile = amp bits 0..10
    // tile bits: 0..2 -> amp 0..2, 3..6 -> amp 4..7, 7..10 -> amp 11..14
    return hi | (a & 7u) | (((a >> 3) & 15u) << 4) | ((a >> 7) << 11);
}

template <int PASS>
__global__ __launch_bounds__(128, 5)
void qsim_pass(const float* __restrict__ in, float* __restrict__ out,
               const float* __restrict__ gates)
{
    __shared__ float2 sm[2048];
    const unsigned tid = threadIdx.x;
    const unsigned b = blockIdx.x;
    // block bits: pass0 -> amp bits 11..23; pass1 -> amp bits {3, 8..10, 15..23}
    const unsigned hi = (PASS == 0)
        ? (b << 11)
        : (((b & 1u) << 3) | (((b >> 1) & 7u) << 8) | ((b >> 4) << 15));

    // ---- Stage: LDG.128 per plane, conflict-free STS.64 ----
    #pragma unroll
    for (int j = 0; j < 4; ++j) {
        unsigned a = (tid + 128u * j) * 4u;
        unsigned g = gmap<PASS>(hi, a);
        float4 r4 = *(const float4*)(in + g);
        float4 m4 = *(const float4*)(in + NSTATE + g);
        sm[SWZ(a + 0)] = make_float2(r4.x, m4.x);
        sm[SWZ(a + 1)] = make_float2(r4.y, m4.y);
        sm[SWZ(a + 2)] = make_float2(r4.z, m4.z);
        sm[SWZ(a + 3)] = make_float2(r4.w, m4.w);
    }
    __syncthreads();

    // ---- Two fused gate pairs ----
    // pass0: gates (0,7),(1,8) -> tile bits <0,1,7,8>; gates (2,9),(3,10) -> <2,3,9,10>
    // pass1: gates (4,11),(5,12) -> tile bits <3,4,7,8>; gates (6,13),(7,14) -> <5,6,9,10>
    if (PASS == 0) apply_pair<0, 1, 7, 8>(sm, tid, gates + 0 * 32, gates + 1 * 32);
    else           apply_pair<3, 4, 7, 8>(sm, tid, gates + 4 * 32, gates + 5 * 32);
    __syncthreads();
    if (PASS == 0) apply_pair<2, 3, 9, 10>(sm, tid, gates + 2 * 32, gates + 3 * 32);
    else           apply_pair<5, 6, 9, 10>(sm, tid, gates + 6 * 32, gates + 7 * 32);
    __syncthreads();

    // ---- Write back: STG.128 per plane ----
    #pragma unroll
    for (int j = 0; j < 4; ++j) {
        unsigned a = (tid + 128u * j) * 4u;
        unsigned g = gmap<PASS>(hi, a);
        float2 v0 = sm[SWZ(a + 0)], v1 = sm[SWZ(a + 1)];
        float2 v2 = sm[SWZ(a + 2)], v3 = sm[SWZ(a + 3)];
        *(float4*)(out + g)          = make_float4(v0.x, v1.x, v2.x, v3.x);
        *(float4*)(out + NSTATE + g) = make_float4(v0.y, v1.y, v2.y, v3.y);
    }
}

extern "C" void kernel_launch(void* const* d_in, const int* in_sizes, int n_in,
                              void* d_out, int out_size)
{
    const float* state = (const float*)d_in[0];   // 2 * 2^24 floats (re, im planes)
    const float* gates = (const float*)d_in[1];   // 8 * 2 * 4 * 4 floats
    float* out = (float*)d_out;

    qsim_pass<0><<<8192, 128>>>(state, out, gates);   // steps 0..3
    qsim_pass<1><<<8192, 128>>>(out, out, gates);     // steps 4..7 (in place, disjoint)
}

// round 10
// speedup vs baseline: 1.1385x; 1.0088x over previous
#include <cuda_runtime.h>

// 24-qubit state-vector sim, 8 two-qubit gates, step s -> qubits (s, s+7).
// R10 = R9 champion + pass0 pair reorder (gates commute within a pass) so the
// final pair <0,1,7,8> writes its register results DIRECTLY to global memory
// as contiguous float4 runs (amp bits 0,1 are offset bits) -- skips the final
// STS + writeout LDS: pass0 smem wavefronts 256 -> 192. Pass1 unchanged (its
// gate bits are all >=4; direct stores would cost more wavefronts than smem).

#define NSTATE (1u << 24)
typedef unsigned long long u64;

__device__ __forceinline__ u64 pk2(float lo, float hi) {
    u64 r; asm("mov.b64 %0, {%1, %2};" : "=l"(r) : "f"(lo), "f"(hi)); return r;
}
__device__ __forceinline__ void upk2(u64 v, float& lo, float& hi) {
    asm("mov.b64 {%0, %1}, %2;" : "=f"(lo), "=f"(hi) : "l"(v));
}
__device__ __forceinline__ u64 ffma2(u64 a, u64 b, u64 c) {
    u64 d; asm("fma.rn.f32x2 %0, %1, %2, %3;" : "=l"(d) : "l"(a), "l"(b), "l"(c)); return d;
}
__device__ __forceinline__ u64 fmul2(u64 a, u64 b) {
    u64 d; asm("mul.rn.f32x2 %0, %1, %2;" : "=l"(d) : "l"(a), "l"(b)); return d;
}
__device__ __forceinline__ u64 fadd2(u64 a, u64 b) {
    u64 d; asm("add.rn.f32x2 %0, %1, %2;" : "=l"(d) : "l"(a), "l"(b)); return d;
}
__device__ __forceinline__ float negf(float v) {
    return __int_as_float(__float_as_int(v) ^ 0x80000000u);
}
__device__ __forceinline__ unsigned SWZ(unsigned x) {
    return x ^ (((x >> 4) & 1u) * 5u) ^ (((x >> 5) & 1u) * 10u);
}

// Complex 4x4 gate on a quad; weights packed (wr,wi). Two-phase A/B form.
__device__ __forceinline__ void gate4(u64& v0, u64& v1, u64& v2, u64& v3,
                                      const u64* __restrict__ w)
{
    float r0,i0,r1,i1,r2,i2,r3,i3;
    upk2(v0,r0,i0); upk2(v1,r1,i1); upk2(v2,r2,i2); upk2(v3,r3,i3);

    u64 P0 = pk2(r0, r0), P1 = pk2(r1, r1), P2 = pk2(r2, r2), P3 = pk2(r3, r3);
    u64 A0 = fmul2(P0, w[0]);
    A0 = ffma2(P1, w[1], A0); A0 = ffma2(P2, w[2], A0); A0 = ffma2(P3, w[3], A0);
    u64 A1 = fmul2(P0, w[4]);
    A1 = ffma2(P1, w[5], A1); A1 = ffma2(P2, w[6], A1); A1 = ffma2(P3, w[7], A1);
    u64 A2 = fmul2(P0, w[8]);
    A2 = ffma2(P1, w[9], A2); A2 = ffma2(P2, w[10], A2); A2 = ffma2(P3, w[11], A2);
    u64 A3 = fmul2(P0, w[12]);
    A3 = ffma2(P1, w[13], A3); A3 = ffma2(P2, w[14], A3); A3 = ffma2(P3, w[15], A3);

    u64 Q0 = pk2(i0, i0), Q1 = pk2(i1, i1), Q2 = pk2(i2, i2), Q3 = pk2(i3, i3);
    {
        u64 B = fmul2(Q0, w[0]);
        B = ffma2(Q1, w[1], B); B = ffma2(Q2, w[2], B); B = ffma2(Q3, w[3], B);
        float bl, bh; upk2(B, bl, bh);
        v0 = fadd2(A0, pk2(negf(bh), bl));
    }
    {
        u64 B = fmul2(Q0, w[4]);
        B = ffma2(Q1, w[5], B); B = ffma2(Q2, w[6], B); B = ffma2(Q3, w[7], B);
        float bl, bh; upk2(B, bl, bh);
        v1 = fadd2(A1, pk2(negf(bh), bl));
    }
    {
        u64 B = fmul2(Q0, w[8]);
        B = ffma2(Q1, w[9], B); B = ffma2(Q2, w[10], B); B = ffma2(Q3, w[11], B);
        float bl, bh; upk2(B, bl, bh);
        v2 = fadd2(A2, pk2(negf(bh), bl));
    }
    {
        u64 B = fmul2(Q0, w[12]);
        B = ffma2(Q1, w[13], B); B = ffma2(Q2, w[14], B); B = ffma2(Q3, w[15], B);
        float bl, bh; upk2(B, bl, bh);
        v3 = fadd2(A3, pk2(negf(bh), bl));
    }
}

__device__ __forceinline__ unsigned expand4(unsigned t, int P0, int P1, int P2, int P3) {
    unsigned x = t;
    x = ((x & ~((1u << P0) - 1u)) << 1) | (x & ((1u << P0) - 1u));
    x = ((x & ~((1u << P1) - 1u)) << 1) | (x & ((1u << P1) - 1u));
    x = ((x & ~((1u << P2) - 1u)) << 1) | (x & ((1u << P2) - 1u));
    x = ((x & ~((1u << P3) - 1u)) << 1) | (x & ((1u << P3) - 1u));
    return x;
}

// Two fused gates on a 16-amp supergroup via smem (load, apply, store).
template <int P0, int P1, int P2, int P3>
__device__ __forceinline__ void apply_pair(float2* sm, unsigned tid,
                                           const float* __restrict__ gp0,
                                           const float* __restrict__ gp1)
{
    const unsigned x = expand4(tid, P0, P1, P2, P3);

    u64 p[16];
    #pragma unroll
    for (int i = 0; i < 16; ++i) {
        unsigned off = ((i & 1)        ? (1u << P0) : 0u)
                     | (((i >> 1) & 1) ? (1u << P1) : 0u)
                     | (((i >> 2) & 1) ? (1u << P2) : 0u)
                     | (((i >> 3) & 1) ? (1u << P3) : 0u);
        float2 v = sm[SWZ(x | off)];
        p[i] = pk2(v.x, v.y);
    }

    {   u64 w[16];
        #pragma unroll
        for (int k = 0; k < 16; ++k)
            w[k] = pk2(__ldg(gp0 + k), __ldg(gp0 + 16 + k));
        gate4(p[0],  p[1],  p[4],  p[5],  w);
        gate4(p[2],  p[3],  p[6],  p[7],  w);
        gate4(p[8],  p[9],  p[12], p[13], w);
        gate4(p[10], p[11], p[14], p[15], w);
    }
    {   u64 w[16];
        #pragma unroll
        for (int k = 0; k < 16; ++k)
            w[k] = pk2(__ldg(gp1 + k), __ldg(gp1 + 16 + k));
        gate4(p[0], p[2], p[8],  p[10], w);
        gate4(p[1], p[3], p[9],  p[11], w);
        gate4(p[4], p[6], p[12], p[14], w);
        gate4(p[5], p[7], p[13], p[15], w);
    }

    #pragma unroll
    for (int i = 0; i < 16; ++i) {
        unsigned off = ((i & 1)        ? (1u << P0) : 0u)
                     | (((i >> 1) & 1) ? (1u << P1) : 0u)
                     | (((i >> 2) & 1) ? (1u << P2) : 0u)
                     | (((i >> 3) & 1) ? (1u << P3) : 0u);
        float lo, hi; upk2(p[i], lo, hi);
        sm[SWZ(x | off)] = make_float2(lo, hi);
    }
}

// ---------------- Pass 0: steps 0..3, tile = amp bits 0..10 ----------------
__global__ __launch_bounds__(128, 5)
void qsim_pass0(const float* __restrict__ in, float* __restrict__ out,
                const float* __restrict__ gates)
{
    __shared__ float2 sm[2048];
    const unsigned tid = threadIdx.x;
    const unsigned hi = blockIdx.x << 11;

    // Stage: LDG.128 per plane, conflict-free STS.64.
    #pragma unroll
    for (int j = 0; j < 4; ++j) {
        unsigned a = (tid + 128u * j) * 4u;
        float4 r4 = *(const float4*)(in + (hi | a));
        float4 m4 = *(const float4*)(in + NSTATE + (hi | a));
        sm[SWZ(a + 0)] = make_float2(r4.x, m4.x);
        sm[SWZ(a + 1)] = make_float2(r4.y, m4.y);
        sm[SWZ(a + 2)] = make_float2(r4.z, m4.z);
        sm[SWZ(a + 3)] = make_float2(r4.w, m4.w);
    }
    __syncthreads();

    // Gates 2,3 first (commuting) -- smem round trip.
    apply_pair<2, 3, 9, 10>(sm, tid, gates + 2 * 32, gates + 3 * 32);
    __syncthreads();

    // Gates 0,1 last: load from smem, apply, write DIRECTLY to global.
    {
        const unsigned x = expand4(tid, 0, 1, 7, 8);
        u64 p[16];
        #pragma unroll
        for (int i = 0; i < 16; ++i) {
            unsigned off = (i & 3u) | (((i >> 2) & 1) << 7) | (((i >> 3) & 1) << 8);
            float2 v = sm[SWZ(x | off)];
            p[i] = pk2(v.x, v.y);
        }
        {   u64 w[16];
            #pragma unroll
            for (int k = 0; k < 16; ++k)
                w[k] = pk2(__ldg(gates + k), __ldg(gates + 16 + k));
            gate4(p[0],  p[1],  p[4],  p[5],  w);   // gate 0: vary bits (0,2)
            gate4(p[2],  p[3],  p[6],  p[7],  w);
            gate4(p[8],  p[9],  p[12], p[13], w);
            gate4(p[10], p[11], p[14], p[15], w);
        }
        {   u64 w[16];
            #pragma unroll
            for (int k = 0; k < 16; ++k)
                w[k] = pk2(__ldg(gates + 32 + k), __ldg(gates + 48 + k));
            gate4(p[0], p[2], p[8],  p[10], w);     // gate 1: vary bits (1,3)
            gate4(p[1], p[3], p[9],  p[11], w);
            gate4(p[4], p[6], p[12], p[14], w);
            gate4(p[5], p[7], p[13], p[15], w);
        }
        // Direct writeout: 4 contiguous float4 runs (amp bits 0,1 are in-run).
        #pragma unroll
        for (int h = 0; h < 4; ++h) {
            unsigned bi = h << 2;                               // i = 4*h2 + 8*h3
            unsigned g = hi | x | ((h & 1u) << 7) | ((h >> 1) << 8);
            float r0,i0,r1,i1,r2,i2,r3,i3;
            upk2(p[bi+0], r0, i0); upk2(p[bi+1], r1, i1);
            upk2(p[bi+2], r2, i2); upk2(p[bi+3], r3, i3);
            *(float4*)(out + g)          = make_float4(r0, r1, r2, r3);
            *(float4*)(out + NSTATE + g) = make_float4(i0, i1, i2, i3);
        }
    }
}

// ---------------- Pass 1: steps 4..7 (R9 verbatim) ----------------
__device__ __forceinline__ unsigned gmap1(unsigned hi, unsigned a) {
    // tile bits: 0..2 -> amp 0..2, 3..6 -> amp 4..7, 7..10 -> amp 11..14
    return hi | (a & 7u) | (((a >> 3) & 15u) << 4) | ((a >> 7) << 11);
}

__global__ __launch_bounds__(128, 5)
void qsim_pass1(float* __restrict__ st, const float* __restrict__ gates)
{
    __shared__ float2 sm[2048];
    const unsigned tid = threadIdx.x;
    const unsigned b = blockIdx.x;
    // block bits -> amp bits {3, 8..10, 15..23}
    const unsigned hi = ((b & 1u) << 3) | (((b >> 1) & 7u) << 8) | ((b >> 4) << 15);

    #pragma unroll
    for (int j = 0; j < 4; ++j) {
        unsigned a = (tid + 128u * j) * 4u;
        unsigned g = gmap1(hi, a);
        float4 r4 = *(const float4*)(st + g);
        float4 m4 = *(const float4*)(st + NSTATE + g);
        sm[SWZ(a + 0)] = make_float2(r4.x, m4.x);
        sm[SWZ(a + 1)] = make_float2(r4.y, m4.y);
        sm[SWZ(a + 2)] = make_float2(r4.z, m4.z);
        sm[SWZ(a + 3)] = make_float2(r4.w, m4.w);
    }
    __syncthreads();

    // gates (4,11),(5,12) -> tile bits <3,4,7,8>; gates (6,13),(7,14) -> <5,6,9,10>
    apply_pair<3, 4, 7, 8>(sm, tid, gates + 4 * 32, gates + 5 * 32);
    __syncthreads();
    apply_pair<5, 6, 9, 10>(sm, tid, gates + 6 * 32, gates + 7 * 32);
    __syncthreads();

    #pragma unroll
    for (int j = 0; j < 4; ++j) {
        unsigned a = (tid + 128u * j) * 4u;
        unsigned g = gmap1(hi, a);
        float2 v0 = sm[SWZ(a + 0)], v1 = sm[SWZ(a + 1)];
        float2 v2 = sm[SWZ(a + 2)], v3 = sm[SWZ(a + 3)];
        *(float4*)(st + g)          = make_float4(v0.x, v1.x, v2.x, v3.x);
        *(float4*)(st + NSTATE + g) = make_float4(v0.y, v1.y, v2.y, v3.y);
    }
}

extern "C" void kernel_launch(void* const* d_in, const int* in_sizes, int n_in,
                              void* d_out, int out_size)
{
    const float* state = (const float*)d_in[0];   // 2 * 2^24 floats (re, im planes)
    const float* gates = (const float*)d_in[1];   // 8 * 2 * 4 * 4 floats
    float* out = (float*)d_out;

    qsim_pass0<<<8192, 128>>>(state, out, gates);   // steps 0..3
    qsim_pass1<<<8192, 128>>>(out, gates);          // steps 4..7 (in place, disjoint)
}

// round 11
// speedup vs baseline: 1.1594x; 1.0184x over previous
#include <cuda_runtime.h>

// 24-qubit state-vector sim, 8 two-qubit gates, step s -> qubits (s, s+7).
// R11: re-partitioned passes so BOTH tiles are contiguous-coalesced:
//  Pass0 = gates 0..4, tile = amp bits {0..5, 7..11} (64-amp contiguous runs):
//    stage -> gate4(4,10) -> pair<2,3,8,9> -> pair<0,1,6,7> + DIRECT global
//    store from registers (offset bits 0,1 -> float4 runs). 4 smem-acc/amp.
//  Pass1 = gates 5..7, tile = amp bits {0..7, 12..14} (256-amp contiguous):
//    stage -> gate7(7,10) -> pair<5,6,8,9> -> writeout. 6 smem-acc/amp, 3 gates.
// SWZ (fold bit4->{0,2}, bit5->{1,3}) verified conflict-free (rank-4 at
// 16-lane phase granularity) for every access pattern in both passes.

#define NSTATE (1u << 24)
typedef unsigned long long u64;

__device__ __forceinline__ u64 pk2(float lo, float hi) {
    u64 r; asm("mov.b64 %0, {%1, %2};" : "=l"(r) : "f"(lo), "f"(hi)); return r;
}
__device__ __forceinline__ void upk2(u64 v, float& lo, float& hi) {
    asm("mov.b64 {%0, %1}, %2;" : "=f"(lo), "=f"(hi) : "l"(v));
}
__device__ __forceinline__ u64 ffma2(u64 a, u64 b, u64 c) {
    u64 d; asm("fma.rn.f32x2 %0, %1, %2, %3;" : "=l"(d) : "l"(a), "l"(b), "l"(c)); return d;
}
__device__ __forceinline__ u64 fmul2(u64 a, u64 b) {
    u64 d; asm("mul.rn.f32x2 %0, %1, %2;" : "=l"(d) : "l"(a), "l"(b)); return d;
}
__device__ __forceinline__ u64 fadd2(u64 a, u64 b) {
    u64 d; asm("add.rn.f32x2 %0, %1, %2;" : "=l"(d) : "l"(a), "l"(b)); return d;
}
__device__ __forceinline__ float negf(float v) {
    return __int_as_float(__float_as_int(v) ^ 0x80000000u);
}
__device__ __forceinline__ unsigned SWZ(unsigned x) {
    return x ^ (((x >> 4) & 1u) * 5u) ^ (((x >> 5) & 1u) * 10u);
}

// Complex 4x4 gate on a quad; weights packed (wr,wi). Two-phase A/B form.
__device__ __forceinline__ void gate4(u64& v0, u64& v1, u64& v2, u64& v3,
                                      const u64* __restrict__ w)
{
    float r0,i0,r1,i1,r2,i2,r3,i3;
    upk2(v0,r0,i0); upk2(v1,r1,i1); upk2(v2,r2,i2); upk2(v3,r3,i3);

    u64 P0 = pk2(r0, r0), P1 = pk2(r1, r1), P2 = pk2(r2, r2), P3 = pk2(r3, r3);
    u64 A0 = fmul2(P0, w[0]);
    A0 = ffma2(P1, w[1], A0); A0 = ffma2(P2, w[2], A0); A0 = ffma2(P3, w[3], A0);
    u64 A1 = fmul2(P0, w[4]);
    A1 = ffma2(P1, w[5], A1); A1 = ffma2(P2, w[6], A1); A1 = ffma2(P3, w[7], A1);
    u64 A2 = fmul2(P0, w[8]);
    A2 = ffma2(P1, w[9], A2); A2 = ffma2(P2, w[10], A2); A2 = ffma2(P3, w[11], A2);
    u64 A3 = fmul2(P0, w[12]);
    A3 = ffma2(P1, w[13], A3); A3 = ffma2(P2, w[14], A3); A3 = ffma2(P3, w[15], A3);

    u64 Q0 = pk2(i0, i0), Q1 = pk2(i1, i1), Q2 = pk2(i2, i2), Q3 = pk2(i3, i3);
    {
        u64 B = fmul2(Q0, w[0]);
        B = ffma2(Q1, w[1], B); B = ffma2(Q2, w[2], B); B = ffma2(Q3, w[3], B);
        float bl, bh; upk2(B, bl, bh);
        v0 = fadd2(A0, pk2(negf(bh), bl));
    }
    {
        u64 B = fmul2(Q0, w[4]);
        B = ffma2(Q1, w[5], B); B = ffma2(Q2, w[6], B); B = ffma2(Q3, w[7], B);
        float bl, bh; upk2(B, bl, bh);
        v1 = fadd2(A1, pk2(negf(bh), bl));
    }
    {
        u64 B = fmul2(Q0, w[8]);
        B = ffma2(Q1, w[9], B); B = ffma2(Q2, w[10], B); B = ffma2(Q3, w[11], B);
        float bl, bh; upk2(B, bl, bh);
        v2 = fadd2(A2, pk2(negf(bh), bl));
    }
    {
        u64 B = fmul2(Q0, w[12]);
        B = ffma2(Q1, w[13], B); B = ffma2(Q2, w[14], B); B = ffma2(Q3, w[15], B);
        float bl, bh; upk2(B, bl, bh);
        v3 = fadd2(A3, pk2(negf(bh), bl));
    }
}

__device__ __forceinline__ unsigned expand4(unsigned t, int P0, int P1, int P2, int P3) {
    unsigned x = t;
    x = ((x & ~((1u << P0) - 1u)) << 1) | (x & ((1u << P0) - 1u));
    x = ((x & ~((1u << P1) - 1u)) << 1) | (x & ((1u << P1) - 1u));
    x = ((x & ~((1u << P2) - 1u)) << 1) | (x & ((1u << P2) - 1u));
    x = ((x & ~((1u << P3) - 1u)) << 1) | (x & ((1u << P3) - 1u));
    return x;
}
__device__ __forceinline__ unsigned expand2(unsigned t, int L, int H) {
    unsigned x = ((t & ~((1u << L) - 1u)) << 1) | (t & ((1u << L) - 1u));
    return ((x & ~((1u << H) - 1u)) << 1) | (x & ((1u << H) - 1u));
}

// Two fused gates on a 16-amp supergroup via smem round trip.
template <int P0, int P1, int P2, int P3>
__device__ __forceinline__ void apply_pair(float2* sm, unsigned tid,
                                           const float* __restrict__ gp0,
                                           const float* __restrict__ gp1)
{
    const unsigned x = expand4(tid, P0, P1, P2, P3);

    u64 p[16];
    #pragma unroll
    for (int i = 0; i < 16; ++i) {
        unsigned off = ((i & 1)        ? (1u << P0) : 0u)
                     | (((i >> 1) & 1) ? (1u << P1) : 0u)
                     | (((i >> 2) & 1) ? (1u << P2) : 0u)
                     | (((i >> 3) & 1) ? (1u << P3) : 0u);
        float2 v = sm[SWZ(x | off)];
        p[i] = pk2(v.x, v.y);
    }

    {   u64 w[16];
        #pragma unroll
        for (int k = 0; k < 16; ++k)
            w[k] = pk2(__ldg(gp0 + k), __ldg(gp0 + 16 + k));
        gate4(p[0],  p[1],  p[4],  p[5],  w);
        gate4(p[2],  p[3],  p[6],  p[7],  w);
        gate4(p[8],  p[9],  p[12], p[13], w);
        gate4(p[10], p[11], p[14], p[15], w);
    }
    {   u64 w[16];
        #pragma unroll
        for (int k = 0; k < 16; ++k)
            w[k] = pk2(__ldg(gp1 + k), __ldg(gp1 + 16 + k));
        gate4(p[0], p[2], p[8],  p[10], w);
        gate4(p[1], p[3], p[9],  p[11], w);
        gate4(p[4], p[6], p[12], p[14], w);
        gate4(p[5], p[7], p[13], p[15], w);
    }

    #pragma unroll
    for (int i = 0; i < 16; ++i) {
        unsigned off = ((i & 1)        ? (1u << P0) : 0u)
                     | (((i >> 1) & 1) ? (1u << P1) : 0u)
                     | (((i >> 2) & 1) ? (1u << P2) : 0u)
                     | (((i >> 3) & 1) ? (1u << P3) : 0u);
        float lo, hi; upk2(p[i], lo, hi);
        sm[SWZ(x | off)] = make_float2(lo, hi);
    }
}

// Single gate on quads at tile bits (L,H): 4 groups per thread, smem round trip.
template <int L, int H>
__device__ __forceinline__ void apply_single(float2* sm, unsigned tid,
                                             const float* __restrict__ gp)
{
    u64 w[16];
    #pragma unroll
    for (int k = 0; k < 16; ++k)
        w[k] = pk2(__ldg(gp + k), __ldg(gp + 16 + k));

    #pragma unroll
    for (int k = 0; k < 4; ++k) {
        unsigned x = expand2(tid + 128u * k, L, H);
        unsigned i0 = SWZ(x),            i1 = SWZ(x | (1u << L));
        unsigned i2 = SWZ(x | (1u << H)), i3 = SWZ(x | (1u << L) | (1u << H));
        float2 a = sm[i0], b = sm[i1], c = sm[i2], d = sm[i3];
        u64 v0 = pk2(a.x, a.y), v1 = pk2(b.x, b.y);
        u64 v2 = pk2(c.x, c.y), v3 = pk2(d.x, d.y);
        gate4(v0, v1, v2, v3, w);
        float lo, hi;
        upk2(v0, lo, hi); sm[i0] = make_float2(lo, hi);
        upk2(v1, lo, hi); sm[i1] = make_float2(lo, hi);
        upk2(v2, lo, hi); sm[i2] = make_float2(lo, hi);
        upk2(v3, lo, hi); sm[i3] = make_float2(lo, hi);
    }
}

// ---- Pass 0: gates 0..4. Tile = amp bits {0..5, 7..11}; block -> {6, 12..23} ----
__global__ __launch_bounds__(128, 5)
void qsim_pass0(const float* __restrict__ in, float* __restrict__ out,
                const float* __restrict__ gates)
{
    __shared__ float2 sm[2048];
    const unsigned tid = threadIdx.x;
    const unsigned b = blockIdx.x;
    const unsigned hi = ((b & 1u) << 6) | ((b >> 1) << 12);

    // Stage: coalesced LDG.128 (64-amp contiguous runs), conflict-free STS.
    #pragma unroll
    for (int j = 0; j < 4; ++j) {
        unsigned a = (tid + 128u * j) * 4u;
        unsigned g = hi | (a & 63u) | ((a >> 6) << 7);
        float4 r4 = *(const float4*)(in + g);
        float4 m4 = *(const float4*)(in + NSTATE + g);
        sm[SWZ(a + 0)] = make_float2(r4.x, m4.x);
        sm[SWZ(a + 1)] = make_float2(r4.y, m4.y);
        sm[SWZ(a + 2)] = make_float2(r4.z, m4.z);
        sm[SWZ(a + 3)] = make_float2(r4.w, m4.w);
    }
    __syncthreads();

    // Gate 4: amp bits (4,11) -> tile (4,10).
    apply_single<4, 10>(sm, tid, gates + 4 * 32);
    __syncthreads();
    // Gates 2,3: amp (2,9),(3,10) -> tile <2,3,8,9>.
    apply_pair<2, 3, 8, 9>(sm, tid, gates + 2 * 32, gates + 3 * 32);
    __syncthreads();

    // Gates 0,1: amp (0,7),(1,8) -> tile <0,1,6,7>. Direct global store.
    {
        const unsigned x = expand4(tid, 0, 1, 6, 7);
        u64 p[16];
        #pragma unroll
        for (int i = 0; i < 16; ++i) {
            unsigned off = (i & 3u) | (((i >> 2) & 1) << 6) | (((i >> 3) & 1) << 7);
            float2 v = sm[SWZ(x | off)];
            p[i] = pk2(v.x, v.y);
        }
        {   u64 w[16];
            #pragma unroll
            for (int k = 0; k < 16; ++k)
                w[k] = pk2(__ldg(gates + k), __ldg(gates + 16 + k));
            gate4(p[0],  p[1],  p[4],  p[5],  w);
            gate4(p[2],  p[3],  p[6],  p[7],  w);
            gate4(p[8],  p[9],  p[12], p[13], w);
            gate4(p[10], p[11], p[14], p[15], w);
        }
        {   u64 w[16];
            #pragma unroll
            for (int k = 0; k < 16; ++k)
                w[k] = pk2(__ldg(gates + 32 + k), __ldg(gates + 48 + k));
            gate4(p[0], p[2], p[8],  p[10], w);
            gate4(p[1], p[3], p[9],  p[11], w);
            gate4(p[4], p[6], p[12], p[14], w);
            gate4(p[5], p[7], p[13], p[15], w);
        }
        #pragma unroll
        for (int h = 0; h < 4; ++h) {
            unsigned bi = h << 2;
            unsigned t = x | ((h & 1u) << 6) | ((h >> 1) << 7);
            unsigned g = hi | (t & 63u) | ((t >> 6) << 7);
            float r0,i0,r1,i1,r2,i2,r3,i3;
            upk2(p[bi+0], r0, i0); upk2(p[bi+1], r1, i1);
            upk2(p[bi+2], r2, i2); upk2(p[bi+3], r3, i3);
            *(float4*)(out + g)          = make_float4(r0, r1, r2, r3);
            *(float4*)(out + NSTATE + g) = make_float4(i0, i1, i2, i3);
        }
    }
}

// ---- Pass 1: gates 5..7. Tile = amp bits {0..7, 12..14}; block -> {8..11, 15..23} ----
__global__ __launch_bounds__(128, 5)
void qsim_pass1(float* __restrict__ st, const float* __restrict__ gates)
{
    __shared__ float2 sm[2048];
    const unsigned tid = threadIdx.x;
    const unsigned b = blockIdx.x;
    const unsigned hi = ((b & 15u) << 8) | ((b >> 4) << 15);

    // Stage: coalesced LDG.128 (256-amp contiguous runs).
    #pragma unroll
    for (int j = 0; j < 4; ++j) {
        unsigned a = (tid + 128u * j) * 4u;
        unsigned g = hi | (a & 255u) | ((a >> 8) << 12);
        float4 r4 = *(const float4*)(st + g);
        float4 m4 = *(const float4*)(st + NSTATE + g);
        sm[SWZ(a + 0)] = make_float2(r4.x, m4.x);
        sm[SWZ(a + 1)] = make_float2(r4.y, m4.y);
        sm[SWZ(a + 2)] = make_float2(r4.z, m4.z);
        sm[SWZ(a + 3)] = make_float2(r4.w, m4.w);
    }
    __syncthreads();

    // Gate 7: amp bits (7,14) -> tile (7,10).
    apply_single<7, 10>(sm, tid, gates + 7 * 32);
    __syncthreads();
    // Gates 5,6: amp (5,12),(6,13) -> tile <5,6,8,9>.
    apply_pair<5, 6, 8, 9>(sm, tid, gates + 5 * 32, gates + 6 * 32);
    __syncthreads();

    // Writeout: coalesced STG.128.
    #pragma unroll
    for (int j = 0; j < 4; ++j) {
        unsigned a = (tid + 128u * j) * 4u;
        unsigned g = hi | (a & 255u) | ((a >> 8) << 12);
        float2 v0 = sm[SWZ(a + 0)], v1 = sm[SWZ(a + 1)];
        float2 v2 = sm[SWZ(a + 2)], v3 = sm[SWZ(a + 3)];
        *(float4*)(st + g)          = make_float4(v0.x, v1.x, v2.x, v3.x);
        *(float4*)(st + NSTATE + g) = make_float4(v0.y, v1.y, v2.y, v3.y);
    }
}

extern "C" void kernel_launch(void* const* d_in, const int* in_sizes, int n_in,
                              void* d_out, int out_size)
{
    const float* state = (const float*)d_in[0];   // 2 * 2^24 floats (re, im planes)
    const float* gates = (const float*)d_in[1];   // 8 * 2 * 4 * 4 floats
    float* out = (float*)d_out;

    qsim_pass0<<<8192, 128>>>(state, out, gates);   // gates 0..4
    qsim_pass1<<<8192, 128>>>(out, gates);          // gates 5..7 (in place, disjoint)
}

// round 12
// speedup vs baseline: 1.3563x; 1.1698x over previous
#include <cuda_runtime.h>

// 24-qubit state-vector sim, 8 two-qubit gates, step s -> qubits (s, s+7).
// R12: fuse first gate with the global LOAD and last gate(s) with the global
// STORE in both passes -- removes the separate stage/writeout smem round trips.
//  Pass0 = gates 0..4, tile = amp bits {0..5,7..11}:
//    ph1: LDG(float4) + gate4(amp 4,11) in regs + STS
//    ph2: pair<2,3,8,9> smem round trip
//    ph3: pair<0,1,6,7> LDS + DIRECT STG.128        (224 wf/warp, was 256)
//  Pass1 = gates 5..7, tile = amp bits {0..7,12..14}:
//    ph1: LDG(float4, perfectly coalesced) + gate7(amp 7,14) + STS
//    ph2: pair<5,6,8,9> LDS + DIRECT STG.32 (128B-coalesced)  (128 wf, was 256)
// SWZ folds tile bits 4,5,6 into bank bits; every LDS/STS pattern verified
// rank-4 (conflict-free) at 16-lane phase granularity.

#define NSTATE (1u << 24)
typedef unsigned long long u64;

__device__ __forceinline__ u64 pk2(float lo, float hi) {
    u64 r; asm("mov.b64 %0, {%1, %2};" : "=l"(r) : "f"(lo), "f"(hi)); return r;
}
__device__ __forceinline__ void upk2(u64 v, float& lo, float& hi) {
    asm("mov.b64 {%0, %1}, %2;" : "=f"(lo), "=f"(hi) : "l"(v));
}
__device__ __forceinline__ u64 ffma2(u64 a, u64 b, u64 c) {
    u64 d; asm("fma.rn.f32x2 %0, %1, %2, %3;" : "=l"(d) : "l"(a), "l"(b), "l"(c)); return d;
}
__device__ __forceinline__ u64 fmul2(u64 a, u64 b) {
    u64 d; asm("mul.rn.f32x2 %0, %1, %2;" : "=l"(d) : "l"(a), "l"(b)); return d;
}
__device__ __forceinline__ u64 fadd2(u64 a, u64 b) {
    u64 d; asm("add.rn.f32x2 %0, %1, %2;" : "=l"(d) : "l"(a), "l"(b)); return d;
}
__device__ __forceinline__ float negf(float v) {
    return __int_as_float(__float_as_int(v) ^ 0x80000000u);
}
// Fold tile bits 4,5,6 into bank bits: idx0^=x4^x6, idx1^=x5, idx2^=x4, idx3^=x5.
__device__ __forceinline__ unsigned SWZ(unsigned x) {
    return x ^ (((x >> 4) & 1u) * 5u) ^ (((x >> 5) & 1u) * 10u)
             ^ (((x >> 6) & 1u) * 1u);
}

// Complex 4x4 gate on a quad; weights packed (wr,wi). Two-phase A/B form.
__device__ __forceinline__ void gate4(u64& v0, u64& v1, u64& v2, u64& v3,
                                      const u64* __restrict__ w)
{
    float r0,i0,r1,i1,r2,i2,r3,i3;
    upk2(v0,r0,i0); upk2(v1,r1,i1); upk2(v2,r2,i2); upk2(v3,r3,i3);

    u64 P0 = pk2(r0, r0), P1 = pk2(r1, r1), P2 = pk2(r2, r2), P3 = pk2(r3, r3);
    u64 A0 = fmul2(P0, w[0]);
    A0 = ffma2(P1, w[1], A0); A0 = ffma2(P2, w[2], A0); A0 = ffma2(P3, w[3], A0);
    u64 A1 = fmul2(P0, w[4]);
    A1 = ffma2(P1, w[5], A1); A1 = ffma2(P2, w[6], A1); A1 = ffma2(P3, w[7], A1);
    u64 A2 = fmul2(P0, w[8]);
    A2 = ffma2(P1, w[9], A2); A2 = ffma2(P2, w[10], A2); A2 = ffma2(P3, w[11], A2);
    u64 A3 = fmul2(P0, w[12]);
    A3 = ffma2(P1, w[13], A3); A3 = ffma2(P2, w[14], A3); A3 = ffma2(P3, w[15], A3);

    u64 Q0 = pk2(i0, i0), Q1 = pk2(i1, i1), Q2 = pk2(i2, i2), Q3 = pk2(i3, i3);
    {
        u64 B = fmul2(Q0, w[0]);
        B = ffma2(Q1, w[1], B); B = ffma2(Q2, w[2], B); B = ffma2(Q3, w[3], B);
        float bl, bh; upk2(B, bl, bh);
        v0 = fadd2(A0, pk2(negf(bh), bl));
    }
    {
        u64 B = fmul2(Q0, w[4]);
        B = ffma2(Q1, w[5], B); B = ffma2(Q2, w[6], B); B = ffma2(Q3, w[7], B);
        float bl, bh; upk2(B, bl, bh);
        v1 = fadd2(A1, pk2(negf(bh), bl));
    }
    {
        u64 B = fmul2(Q0, w[8]);
        B = ffma2(Q1, w[9], B); B = ffma2(Q2, w[10], B); B = ffma2(Q3, w[11], B);
        float bl, bh; upk2(B, bl, bh);
        v2 = fadd2(A2, pk2(negf(bh), bl));
    }
    {
        u64 B = fmul2(Q0, w[12]);
        B = ffma2(Q1, w[13], B); B = ffma2(Q2, w[14], B); B = ffma2(Q3, w[15], B);
        float bl, bh; upk2(B, bl, bh);
        v3 = fadd2(A3, pk2(negf(bh), bl));
    }
}

__device__ __forceinline__ unsigned expand4(unsigned t, int P0, int P1, int P2, int P3) {
    unsigned x = t;
    x = ((x & ~((1u << P0) - 1u)) << 1) | (x & ((1u << P0) - 1u));
    x = ((x & ~((1u << P1) - 1u)) << 1) | (x & ((1u << P1) - 1u));
    x = ((x & ~((1u << P2) - 1u)) << 1) | (x & ((1u << P2) - 1u));
    x = ((x & ~((1u << P3) - 1u)) << 1) | (x & ((1u << P3) - 1u));
    return x;
}

// Two fused gates on a 16-amp supergroup via smem round trip.
template <int P0, int P1, int P2, int P3>
__device__ __forceinline__ void apply_pair(float2* sm, unsigned tid,
                                           const float* __restrict__ gp0,
                                           const float* __restrict__ gp1)
{
    const unsigned x = expand4(tid, P0, P1, P2, P3);

    u64 p[16];
    #pragma unroll
    for (int i = 0; i < 16; ++i) {
        unsigned off = ((i & 1)        ? (1u << P0) : 0u)
                     | (((i >> 1) & 1) ? (1u << P1) : 0u)
                     | (((i >> 2) & 1) ? (1u << P2) : 0u)
                     | (((i >> 3) & 1) ? (1u << P3) : 0u);
        float2 v = sm[SWZ(x | off)];
        p[i] = pk2(v.x, v.y);
    }

    {   u64 w[16];
        #pragma unroll
        for (int k = 0; k < 16; ++k)
            w[k] = pk2(__ldg(gp0 + k), __ldg(gp0 + 16 + k));
        gate4(p[0],  p[1],  p[4],  p[5],  w);
        gate4(p[2],  p[3],  p[6],  p[7],  w);
        gate4(p[8],  p[9],  p[12], p[13], w);
        gate4(p[10], p[11], p[14], p[15], w);
    }
    {   u64 w[16];
        #pragma unroll
        for (int k = 0; k < 16; ++k)
            w[k] = pk2(__ldg(gp1 + k), __ldg(gp1 + 16 + k));
        gate4(p[0], p[2], p[8],  p[10], w);
        gate4(p[1], p[3], p[9],  p[11], w);
        gate4(p[4], p[6], p[12], p[14], w);
        gate4(p[5], p[7], p[13], p[15], w);
    }

    #pragma unroll
    for (int i = 0; i < 16; ++i) {
        unsigned off = ((i & 1)        ? (1u << P0) : 0u)
                     | (((i >> 1) & 1) ? (1u << P1) : 0u)
                     | (((i >> 2) & 1) ? (1u << P2) : 0u)
                     | (((i >> 3) & 1) ? (1u << P3) : 0u);
        float lo, hi; upk2(p[i], lo, hi);
        sm[SWZ(x | off)] = make_float2(lo, hi);
    }
}

// ---- Pass 0: gates 0..4. Tile = amp bits {0..5, 7..11}; block -> {6, 12..23} ----
// g(a) = hi | (a & 63) | ((a >> 6) << 7)
__global__ __launch_bounds__(128, 5)
void qsim_pass0(const float* __restrict__ in, float* __restrict__ out,
                const float* __restrict__ gates)
{
    __shared__ float2 sm[2048];
    const unsigned t = threadIdx.x;
    const unsigned b = blockIdx.x;
    const unsigned hi = ((b & 1u) << 6) | ((b >> 1) << 12);

    // Phase 1: fused LDG + gate4 (amp bits 4,11 -> tile 4,10) + STS.
    {
        u64 w[16];
        #pragma unroll
        for (int k = 0; k < 16; ++k)
            w[k] = pk2(__ldg(gates + 4 * 32 + k), __ldg(gates + 4 * 32 + 16 + k));

        const unsigned B = ((t & 3u) << 2) | ((t >> 2) << 5);   // tile bits 2,3 + 5..9
        u64 p[16];   // i = f + 4*q0 + 8*q1 ; f = amp bits 0,1
        #pragma unroll
        for (int q = 0; q < 4; ++q) {
            unsigned a0 = B | ((q & 1u) << 4) | ((unsigned)(q >> 1) << 10);
            unsigned g = hi | (a0 & 63u) | ((a0 >> 6) << 7);
            float4 r4 = *(const float4*)(in + g);
            float4 m4 = *(const float4*)(in + NSTATE + g);
            p[q * 4 + 0] = pk2(r4.x, m4.x);
            p[q * 4 + 1] = pk2(r4.y, m4.y);
            p[q * 4 + 2] = pk2(r4.z, m4.z);
            p[q * 4 + 3] = pk2(r4.w, m4.w);
        }
        #pragma unroll
        for (int f = 0; f < 4; ++f)
            gate4(p[f], p[f + 4], p[f + 8], p[f + 12], w);
        #pragma unroll
        for (int i = 0; i < 16; ++i) {
            unsigned a = B | (unsigned)(i & 3)
                       | (((unsigned)(i >> 2) & 1u) << 4)
                       | (((unsigned)(i >> 3) & 1u) << 10);
            float lo, hic; upk2(p[i], lo, hic);
            sm[SWZ(a)] = make_float2(lo, hic);
        }
    }
    __syncthreads();

    // Phase 2: gates 2,3 (amp (2,9),(3,10) -> tile <2,3,8,9>), smem round trip.
    apply_pair<2, 3, 8, 9>(sm, t, gates + 2 * 32, gates + 3 * 32);
    __syncthreads();

    // Phase 3: gates 0,1 (amp (0,7),(1,8) -> tile <0,1,6,7>), direct STG.128.
    {
        const unsigned x = expand4(t, 0, 1, 6, 7);
        u64 p[16];
        #pragma unroll
        for (int i = 0; i < 16; ++i) {
            unsigned off = (i & 3u) | (((i >> 2) & 1) << 6) | (((i >> 3) & 1) << 7);
            float2 v = sm[SWZ(x | off)];
            p[i] = pk2(v.x, v.y);
        }
        {   u64 w[16];
            #pragma unroll
            for (int k = 0; k < 16; ++k)
                w[k] = pk2(__ldg(gates + k), __ldg(gates + 16 + k));
            gate4(p[0],  p[1],  p[4],  p[5],  w);
            gate4(p[2],  p[3],  p[6],  p[7],  w);
            gate4(p[8],  p[9],  p[12], p[13], w);
            gate4(p[10], p[11], p[14], p[15], w);
        }
        {   u64 w[16];
            #pragma unroll
            for (int k = 0; k < 16; ++k)
                w[k] = pk2(__ldg(gates + 32 + k), __ldg(gates + 48 + k));
            gate4(p[0], p[2], p[8],  p[10], w);
            gate4(p[1], p[3], p[9],  p[11], w);
            gate4(p[4], p[6], p[12], p[14], w);
            gate4(p[5], p[7], p[13], p[15], w);
        }
        #pragma unroll
        for (int h = 0; h < 4; ++h) {
            unsigned bi = h << 2;
            unsigned a = x | ((h & 1u) << 6) | ((unsigned)(h >> 1) << 7);
            unsigned g = hi | (a & 63u) | ((a >> 6) << 7);
            float r0,i0,r1,i1,r2,i2,r3,i3;
            upk2(p[bi+0], r0, i0); upk2(p[bi+1], r1, i1);
            upk2(p[bi+2], r2, i2); upk2(p[bi+3], r3, i3);
            *(float4*)(out + g)          = make_float4(r0, r1, r2, r3);
            *(float4*)(out + NSTATE + g) = make_float4(i0, i1, i2, i3);
        }
    }
}

// ---- Pass 1: gates 5..7. Tile = amp bits {0..7, 12..14}; block -> {8..11, 15..23} ----
// g(a) = hi | (a & 255) | ((a >> 8) << 12)
__global__ __launch_bounds__(128, 5)
void qsim_pass1(float* __restrict__ st, const float* __restrict__ gates)
{
    __shared__ float2 sm[2048];
    const unsigned t = threadIdx.x;
    const unsigned b = blockIdx.x;
    const unsigned hi = ((b & 15u) << 8) | ((b >> 4) << 15);

    // Phase 1: fused LDG (perfectly coalesced) + gate7 (amp 7,14 -> tile 7,10) + STS.
    {
        u64 w[16];
        #pragma unroll
        for (int k = 0; k < 16; ++k)
            w[k] = pk2(__ldg(gates + 7 * 32 + k), __ldg(gates + 7 * 32 + 16 + k));

        const unsigned B = ((t & 31u) << 2) | (((t >> 5) & 3u) << 8);  // tile 2..6 + 8,9
        u64 p[16];   // i = f + 4*q0 + 8*q1
        #pragma unroll
        for (int q = 0; q < 4; ++q) {
            unsigned a0 = B | ((q & 1u) << 7) | ((unsigned)(q >> 1) << 10);
            unsigned g = hi | (a0 & 255u) | ((a0 >> 8) << 12);
            float4 r4 = *(const float4*)(st + g);
            float4 m4 = *(const float4*)(st + NSTATE + g);
            p[q * 4 + 0] = pk2(r4.x, m4.x);
            p[q * 4 + 1] = pk2(r4.y, m4.y);
            p[q * 4 + 2] = pk2(r4.z, m4.z);
            p[q * 4 + 3] = pk2(r4.w, m4.w);
        }
        #pragma unroll
        for (int f = 0; f < 4; ++f)
            gate4(p[f], p[f + 4], p[f + 8], p[f + 12], w);
        #pragma unroll
        for (int i = 0; i < 16; ++i) {
            unsigned a = B | (unsigned)(i & 3)
                       | (((unsigned)(i >> 2) & 1u) << 7)
                       | (((unsigned)(i >> 3) & 1u) << 10);
            float lo, hic; upk2(p[i], lo, hic);
            sm[SWZ(a)] = make_float2(lo, hic);
        }
    }
    __syncthreads();

    // Phase 2: gates 5,6 (amp (5,12),(6,13) -> tile <5,6,8,9>) + direct STG.32.
    {
        const unsigned x = expand4(t, 5, 6, 8, 9);
        u64 p[16];
        #pragma unroll
        for (int i = 0; i < 16; ++i) {
            unsigned off = ((i & 1u) << 5) | (((i >> 1) & 1u) << 6)
                         | (((i >> 2) & 1u) << 8) | (((i >> 3) & 1u) << 9);
            float2 v = sm[SWZ(x | off)];
            p[i] = pk2(v.x, v.y);
        }
        {   u64 w[16];
            #pragma unroll
            for (int k = 0; k < 16; ++k)
                w[k] = pk2(__ldg(gates + 5 * 32 + k), __ldg(gates + 5 * 32 + 16 + k));
            gate4(p[0],  p[1],  p[4],  p[5],  w);   // gate 5: vary i bits (0,2)
            gate4(p[2],  p[3],  p[6],  p[7],  w);
            gate4(p[8],  p[9],  p[12], p[13], w);
            gate4(p[10], p[11], p[14], p[15], w);
        }
        {   u64 w[16];
            #pragma unroll
            for (int k = 0; k < 16; ++k)
                w[k] = pk2(__ldg(gates + 6 * 32 + k), __ldg(gates + 6 * 32 + 16 + k));
            gate4(p[0], p[2], p[8],  p[10], w);     // gate 6: vary i bits (1,3)
            gate4(p[1], p[3], p[9],  p[11], w);
            gate4(p[4], p[6], p[12], p[14], w);
            gate4(p[5], p[7], p[13], p[15], w);
        }
        #pragma unroll
        for (int i = 0; i < 16; ++i) {
            unsigned off = ((i & 1u) << 5) | (((i >> 1) & 1u) << 6)
                         | (((i >> 2) & 1u) << 8) | (((i >> 3) & 1u) << 9);
            unsigned a = x | off;
            unsigned g = hi | (a & 255u) | ((a >> 8) << 12);
            float lo, hic; upk2(p[i], lo, hic);
            st[g] = lo;               // lanes cover amp bits 0..4 -> 128B coalesced
            st[NSTATE + g] = hic;
        }
    }
}

extern "C" void kernel_launch(void* const* d_in, const int* in_sizes, int n_in,
                              void* d_out, int out_size)
{
    const float* state = (const float*)d_in[0];   // 2 * 2^24 floats (re, im planes)
    const float* gates = (const float*)d_in[1];   // 8 * 2 * 4 * 4 floats
    float* out = (float*)d_out;

    qsim_pass0<<<8192, 128>>>(state, out, gates);   // gates 0..4
    qsim_pass1<<<8192, 128>>>(out, gates);          // gates 5..7 (in place, disjoint)
}

// round 14
// speedup vs baseline: 1.3596x; 1.0024x over previous
#include <cuda_runtime.h>

// 24-qubit state-vector sim, 8 two-qubit gates, step s -> qubits (s, s+7).
// R14 = R12 + L2 residency hints via createpolicy + L2::cache_hint (sm_103a
// ptxas rejects inline .L2::evict_* on .v4.f32 -- R13's compile failure):
//   pass0 input reads  : ld.global.nc + evict_first policy (stream, no reuse)
//   pass0 output writes: st.global + evict_last policy (re-read by pass1;
//                        L2 = 126MB ~ full intermediate state)
//   pass1 reads        : ld.global + evict_first policy (consume + demote)
// Structure identical to R12 (107.2us champion).

#define NSTATE (1u << 24)
typedef unsigned long long u64;

__device__ __forceinline__ u64 pk2(float lo, float hi) {
    u64 r; asm("mov.b64 %0, {%1, %2};" : "=l"(r) : "f"(lo), "f"(hi)); return r;
}
__device__ __forceinline__ void upk2(u64 v, float& lo, float& hi) {
    asm("mov.b64 {%0, %1}, %2;" : "=f"(lo), "=f"(hi) : "l"(v));
}
__device__ __forceinline__ u64 ffma2(u64 a, u64 b, u64 c) {
    u64 d; asm("fma.rn.f32x2 %0, %1, %2, %3;" : "=l"(d) : "l"(a), "l"(b), "l"(c)); return d;
}
__device__ __forceinline__ u64 fmul2(u64 a, u64 b) {
    u64 d; asm("mul.rn.f32x2 %0, %1, %2;" : "=l"(d) : "l"(a), "l"(b)); return d;
}
__device__ __forceinline__ u64 fadd2(u64 a, u64 b) {
    u64 d; asm("add.rn.f32x2 %0, %1, %2;" : "=l"(d) : "l"(a), "l"(b)); return d;
}
__device__ __forceinline__ float negf(float v) {
    return __int_as_float(__float_as_int(v) ^ 0x80000000u);
}
__device__ __forceinline__ unsigned SWZ(unsigned x) {
    return x ^ (((x >> 4) & 1u) * 5u) ^ (((x >> 5) & 1u) * 10u)
             ^ (((x >> 6) & 1u) * 1u);
}

// ---- L2 residency policies (created once per thread, reused) ----
__device__ __forceinline__ u64 mkpol_evict_first() {
    u64 p; asm("createpolicy.fractional.L2::evict_first.b64 %0, 1.0;" : "=l"(p));
    return p;
}
__device__ __forceinline__ u64 mkpol_evict_last() {
    u64 p; asm("createpolicy.fractional.L2::evict_last.b64 %0, 1.0;" : "=l"(p));
    return p;
}
__device__ __forceinline__ float4 ldg_stream(const float* p, u64 pol) {  // read-once
    float4 v;
    asm volatile("ld.global.nc.L2::cache_hint.v4.f32 {%0,%1,%2,%3}, [%4], %5;"
                 : "=f"(v.x), "=f"(v.y), "=f"(v.z), "=f"(v.w) : "l"(p), "l"(pol));
    return v;
}
__device__ __forceinline__ float4 ldg_consume(const float* p, u64 pol) { // read+demote
    float4 v;
    asm volatile("ld.global.L2::cache_hint.v4.f32 {%0,%1,%2,%3}, [%4], %5;"
                 : "=f"(v.x), "=f"(v.y), "=f"(v.z), "=f"(v.w) : "l"(p), "l"(pol));
    return v;
}
__device__ __forceinline__ void stg_keep(float* p, float4 v, u64 pol) {  // pin in L2
    asm volatile("st.global.L2::cache_hint.v4.f32 [%0], {%1,%2,%3,%4}, %5;"
                 :: "l"(p), "f"(v.x), "f"(v.y), "f"(v.z), "f"(v.w), "l"(pol)
                 : "memory");
}

// Complex 4x4 gate on a quad; weights packed (wr,wi). Two-phase A/B form.
__device__ __forceinline__ void gate4(u64& v0, u64& v1, u64& v2, u64& v3,
                                      const u64* __restrict__ w)
{
    float r0,i0,r1,i1,r2,i2,r3,i3;
    upk2(v0,r0,i0); upk2(v1,r1,i1); upk2(v2,r2,i2); upk2(v3,r3,i3);

    u64 P0 = pk2(r0, r0), P1 = pk2(r1, r1), P2 = pk2(r2, r2), P3 = pk2(r3, r3);
    u64 A0 = fmul2(P0, w[0]);
    A0 = ffma2(P1, w[1], A0); A0 = ffma2(P2, w[2], A0); A0 = ffma2(P3, w[3], A0);
    u64 A1 = fmul2(P0, w[4]);
    A1 = ffma2(P1, w[5], A1); A1 = ffma2(P2, w[6], A1); A1 = ffma2(P3, w[7], A1);
    u64 A2 = fmul2(P0, w[8]);
    A2 = ffma2(P1, w[9], A2); A2 = ffma2(P2, w[10], A2); A2 = ffma2(P3, w[11], A2);
    u64 A3 = fmul2(P0, w[12]);
    A3 = ffma2(P1, w[13], A3); A3 = ffma2(P2, w[14], A3); A3 = ffma2(P3, w[15], A3);

    u64 Q0 = pk2(i0, i0), Q1 = pk2(i1, i1), Q2 = pk2(i2, i2), Q3 = pk2(i3, i3);
    {
        u64 B = fmul2(Q0, w[0]);
        B = ffma2(Q1, w[1], B); B = ffma2(Q2, w[2], B); B = ffma2(Q3, w[3], B);
        float bl, bh; upk2(B, bl, bh);
        v0 = fadd2(A0, pk2(negf(bh), bl));
    }
    {
        u64 B = fmul2(Q0, w[4]);
        B = ffma2(Q1, w[5], B); B = ffma2(Q2, w[6], B); B = ffma2(Q3, w[7], B);
        float bl, bh; upk2(B, bl, bh);
        v1 = fadd2(A1, pk2(negf(bh), bl));
    }
    {
        u64 B = fmul2(Q0, w[8]);
        B = ffma2(Q1, w[9], B); B = ffma2(Q2, w[10], B); B = ffma2(Q3, w[11], B);
        float bl, bh; upk2(B, bl, bh);
        v2 = fadd2(A2, pk2(negf(bh), bl));
    }
    {
        u64 B = fmul2(Q0, w[12]);
        B = ffma2(Q1, w[13], B); B = ffma2(Q2, w[14], B); B = ffma2(Q3, w[15], B);
        float bl, bh; upk2(B, bl, bh);
        v3 = fadd2(A3, pk2(negf(bh), bl));
    }
}

__device__ __forceinline__ unsigned expand4(unsigned t, int P0, int P1, int P2, int P3) {
    unsigned x = t;
    x = ((x & ~((1u << P0) - 1u)) << 1) | (x & ((1u << P0) - 1u));
    x = ((x & ~((1u << P1) - 1u)) << 1) | (x & ((1u << P1) - 1u));
    x = ((x & ~((1u << P2) - 1u)) << 1) | (x & ((1u << P2) - 1u));
    x = ((x & ~((1u << P3) - 1u)) << 1) | (x & ((1u << P3) - 1u));
    return x;
}

// Two fused gates on a 16-amp supergroup via smem round trip.
template <int P0, int P1, int P2, int P3>
__device__ __forceinline__ void apply_pair(float2* sm, unsigned tid,
                                           const float* __restrict__ gp0,
                                           const float* __restrict__ gp1)
{
    const unsigned x = expand4(tid, P0, P1, P2, P3);

    u64 p[16];
    #pragma unroll
    for (int i = 0; i < 16; ++i) {
        unsigned off = ((i & 1)        ? (1u << P0) : 0u)
                     | (((i >> 1) & 1) ? (1u << P1) : 0u)
                     | (((i >> 2) & 1) ? (1u << P2) : 0u)
                     | (((i >> 3) & 1) ? (1u << P3) : 0u);
        float2 v = sm[SWZ(x | off)];
        p[i] = pk2(v.x, v.y);
    }

    {   u64 w[16];
        #pragma unroll
        for (int k = 0; k < 16; ++k)
            w[k] = pk2(__ldg(gp0 + k), __ldg(gp0 + 16 + k));
        gate4(p[0],  p[1],  p[4],  p[5],  w);
        gate4(p[2],  p[3],  p[6],  p[7],  w);
        gate4(p[8],  p[9],  p[12], p[13], w);
        gate4(p[10], p[11], p[14], p[15], w);
    }
    {   u64 w[16];
        #pragma unroll
        for (int k = 0; k < 16; ++k)
            w[k] = pk2(__ldg(gp1 + k), __ldg(gp1 + 16 + k));
        gate4(p[0], p[2], p[8],  p[10], w);
        gate4(p[1], p[3], p[9],  p[11], w);
        gate4(p[4], p[6], p[12], p[14], w);
        gate4(p[5], p[7], p[13], p[15], w);
    }

    #pragma unroll
    for (int i = 0; i < 16; ++i) {
        unsigned off = ((i & 1)        ? (1u << P0) : 0u)
                     | (((i >> 1) & 1) ? (1u << P1) : 0u)
                     | (((i >> 2) & 1) ? (1u << P2) : 0u)
                     | (((i >> 3) & 1) ? (1u << P3) : 0u);
        float lo, hi; upk2(p[i], lo, hi);
        sm[SWZ(x | off)] = make_float2(lo, hi);
    }
}

// ---- Pass 0: gates 0..4. Tile = amp bits {0..5, 7..11}; block -> {6, 12..23} ----
__global__ __launch_bounds__(128, 5)
void qsim_pass0(const float* __restrict__ in, float* __restrict__ out,
                const float* __restrict__ gates)
{
    __shared__ float2 sm[2048];
    const unsigned t = threadIdx.x;
    const unsigned b = blockIdx.x;
    const unsigned hi = ((b & 1u) << 6) | ((b >> 1) << 12);

    // Phase 1: fused LDG (stream) + gate4 (amp 4,11 -> tile 4,10) + STS.
    {
        const u64 polF = mkpol_evict_first();
        u64 w[16];
        #pragma unroll
        for (int k = 0; k < 16; ++k)
            w[k] = pk2(__ldg(gates + 4 * 32 + k), __ldg(gates + 4 * 32 + 16 + k));

        const unsigned B = ((t & 3u) << 2) | ((t >> 2) << 5);   // tile bits 2,3 + 5..9
        u64 p[16];
        #pragma unroll
        for (int q = 0; q < 4; ++q) {
            unsigned a0 = B | ((q & 1u) << 4) | ((unsigned)(q >> 1) << 10);
            unsigned g = hi | (a0 & 63u) | ((a0 >> 6) << 7);
            float4 r4 = ldg_stream(in + g, polF);
            float4 m4 = ldg_stream(in + NSTATE + g, polF);
            p[q * 4 + 0] = pk2(r4.x, m4.x);
            p[q * 4 + 1] = pk2(r4.y, m4.y);
            p[q * 4 + 2] = pk2(r4.z, m4.z);
            p[q * 4 + 3] = pk2(r4.w, m4.w);
        }
        #pragma unroll
        for (int f = 0; f < 4; ++f)
            gate4(p[f], p[f + 4], p[f + 8], p[f + 12], w);
        #pragma unroll
        for (int i = 0; i < 16; ++i) {
            unsigned a = B | (unsigned)(i & 3)
                       | (((unsigned)(i >> 2) & 1u) << 4)
                       | (((unsigned)(i >> 3) & 1u) << 10);
            float lo, hic; upk2(p[i], lo, hic);
            sm[SWZ(a)] = make_float2(lo, hic);
        }
    }
    __syncthreads();

    // Phase 2: gates 2,3 -> tile <2,3,8,9>, smem round trip.
    apply_pair<2, 3, 8, 9>(sm, t, gates + 2 * 32, gates + 3 * 32);
    __syncthreads();

    // Phase 3: gates 0,1 -> tile <0,1,6,7>, direct STG.128 pinned in L2.
    {
        const u64 polL = mkpol_evict_last();
        const unsigned x = expand4(t, 0, 1, 6, 7);
        u64 p[16];
        #pragma unroll
        for (int i = 0; i < 16; ++i) {
            unsigned off = (i & 3u) | (((i >> 2) & 1) << 6) | (((i >> 3) & 1) << 7);
            float2 v = sm[SWZ(x | off)];
            p[i] = pk2(v.x, v.y);
        }
        {   u64 w[16];
            #pragma unroll
            for (int k = 0; k < 16; ++k)
                w[k] = pk2(__ldg(gates + k), __ldg(gates + 16 + k));
            gate4(p[0],  p[1],  p[4],  p[5],  w);
            gate4(p[2],  p[3],  p[6],  p[7],  w);
            gate4(p[8],  p[9],  p[12], p[13], w);
            gate4(p[10], p[11], p[14], p[15], w);
        }
        {   u64 w[16];
            #pragma unroll
            for (int k = 0; k < 16; ++k)
                w[k] = pk2(__ldg(gates + 32 + k), __ldg(gates + 48 + k));
            gate4(p[0], p[2], p[8],  p[10], w);
            gate4(p[1], p[3], p[9],  p[11], w);
            gate4(p[4], p[6], p[12], p[14], w);
            gate4(p[5], p[7], p[13], p[15], w);
        }
        #pragma unroll
        for (int h = 0; h < 4; ++h) {
            unsigned bi = h << 2;
            unsigned a = x | ((h & 1u) << 6) | ((unsigned)(h >> 1) << 7);
            unsigned g = hi | (a & 63u) | ((a >> 6) << 7);
            float r0,i0,r1,i1,r2,i2,r3,i3;
            upk2(p[bi+0], r0, i0); upk2(p[bi+1], r1, i1);
            upk2(p[bi+2], r2, i2); upk2(p[bi+3], r3, i3);
            stg_keep(out + g,          make_float4(r0, r1, r2, r3), polL);
            stg_keep(out + NSTATE + g, make_float4(i0, i1, i2, i3), polL);
        }
    }
}

// ---- Pass 1: gates 5..7. Tile = amp bits {0..7, 12..14}; block -> {8..11, 15..23} ----
__global__ __launch_bounds__(128, 5)
void qsim_pass1(float* __restrict__ st, const float* __restrict__ gates)
{
    __shared__ float2 sm[2048];
    const unsigned t = threadIdx.x;
    const unsigned b = blockIdx.x;
    const unsigned hi = ((b & 15u) << 8) | ((b >> 4) << 15);

    // Phase 1: fused LDG (consume from L2) + gate7 (amp 7,14 -> tile 7,10) + STS.
    {
        const u64 polF = mkpol_evict_first();
        u64 w[16];
        #pragma unroll
        for (int k = 0; k < 16; ++k)
            w[k] = pk2(__ldg(gates + 7 * 32 + k), __ldg(gates + 7 * 32 + 16 + k));

        const unsigned B = ((t & 31u) << 2) | (((t >> 5) & 3u) << 8);  // tile 2..6 + 8,9
        u64 p[16];
        #pragma unroll
        for (int q = 0; q < 4; ++q) {
            unsigned a0 = B | ((q & 1u) << 7) | ((unsigned)(q >> 1) << 10);
            unsigned g = hi | (a0 & 255u) | ((a0 >> 8) << 12);
            float4 r4 = ldg_consume(st + g, polF);
            float4 m4 = ldg_consume(st + NSTATE + g, polF);
            p[q * 4 + 0] = pk2(r4.x, m4.x);
            p[q * 4 + 1] = pk2(r4.y, m4.y);
            p[q * 4 + 2] = pk2(r4.z, m4.z);
            p[q * 4 + 3] = pk2(r4.w, m4.w);
        }
        #pragma unroll
        for (int f = 0; f < 4; ++f)
            gate4(p[f], p[f + 4], p[f + 8], p[f + 12], w);
        #pragma unroll
        for (int i = 0; i < 16; ++i) {
            unsigned a = B | (unsigned)(i & 3)
                       | (((unsigned)(i >> 2) & 1u) << 7)
                       | (((unsigned)(i >> 3) & 1u) << 10);
            float lo, hic; upk2(p[i], lo, hic);
            sm[SWZ(a)] = make_float2(lo, hic);
        }
    }
    __syncthreads();

    // Phase 2: gates 5,6 -> tile <5,6,8,9>, LDS + direct STG.32 (128B-coalesced).
    {
        const unsigned x = expand4(t, 5, 6, 8, 9);
        u64 p[16];
        #pragma unroll
        for (int i = 0; i < 16; ++i) {
            unsigned off = ((i & 1u) << 5) | (((i >> 1) & 1u) << 6)
                         | (((i >> 2) & 1u) << 8) | (((i >> 3) & 1u) << 9);
            float2 v = sm[SWZ(x | off)];
            p[i] = pk2(v.x, v.y);
        }
        {   u64 w[16];
            #pragma unroll
            for (int k = 0; k < 16; ++k)
                w[k] = pk2(__ldg(gates + 5 * 32 + k), __ldg(gates + 5 * 32 + 16 + k));
            gate4(p[0],  p[1],  p[4],  p[5],  w);
            gate4(p[2],  p[3],  p[6],  p[7],  w);
            gate4(p[8],  p[9],  p[12], p[13], w);
            gate4(p[10], p[11], p[14], p[15], w);
        }
        {   u64 w[16];
            #pragma unroll
            for (int k = 0; k < 16; ++k)
                w[k] = pk2(__ldg(gates + 6 * 32 + k), __ldg(gates + 6 * 32 + 16 + k));
            gate4(p[0], p[2], p[8],  p[10], w);
            gate4(p[1], p[3], p[9],  p[11], w);
            gate4(p[4], p[6], p[12], p[14], w);
            gate4(p[5], p[7], p[13], p[15], w);
        }
        #pragma unroll
        for (int i = 0; i < 16; ++i) {
            unsigned off = ((i & 1u) << 5) | (((i >> 1) & 1u) << 6)
                         | (((i >> 2) & 1u) << 8) | (((i >> 3) & 1u) << 9);
            unsigned a = x | off;
            unsigned g = hi | (a & 255u) | ((a >> 8) << 12);
            float lo, hic; upk2(p[i], lo, hic);
            st[g] = lo;
            st[NSTATE + g] = hic;
        }
    }
}

extern "C" void kernel_launch(void* const* d_in, const int* in_sizes, int n_in,
                              void* d_out, int out_size)
{
    const float* state = (const float*)d_in[0];   // 2 * 2^24 floats (re, im planes)
    const float* gates = (const float*)d_in[1];   // 8 * 2 * 4 * 4 floats
    float* out = (float*)d_out;

    qsim_pass0<<<8192, 128>>>(state, out, gates);   // gates 0..4
    qsim_pass1<<<8192, 128>>>(out, gates);          // gates 5..7 (in place, disjoint)
}

// round 15
// speedup vs baseline: 1.4479x; 1.0650x over previous
#include <cuda_runtime.h>
#include <cuda_fp16.h>

// 24-qubit state-vector sim, 8 two-qubit gates, step s -> qubits (s, s+7).
// R15 = R14 + fp16 (half2-packed) intermediate state in a 64MB __device__
// scratch across the pass boundary:
//   - traffic 512MB -> 384MB (-25%)
//   - 64MB intermediate FITS the 126MB L2, so the evict_last/evict_first
//     policies (neutral in R14 at 128MB) can now actually hold it resident.
// Precision: boundary RMS ~0.03 sits mid-fp16-range; RN rel err ~2.8e-4,
// budget 1e-3. Structure otherwise identical to R12/R14 champion.

#define NSTATE (1u << 24)
typedef unsigned long long u64;

static __device__ __align__(16) unsigned g_mid[1u << 24];   // half2 per amp, 64MB

__device__ __forceinline__ u64 pk2(float lo, float hi) {
    u64 r; asm("mov.b64 %0, {%1, %2};" : "=l"(r) : "f"(lo), "f"(hi)); return r;
}
__device__ __forceinline__ void upk2(u64 v, float& lo, float& hi) {
    asm("mov.b64 {%0, %1}, %2;" : "=f"(lo), "=f"(hi) : "l"(v));
}
__device__ __forceinline__ u64 ffma2(u64 a, u64 b, u64 c) {
    u64 d; asm("fma.rn.f32x2 %0, %1, %2, %3;" : "=l"(d) : "l"(a), "l"(b), "l"(c)); return d;
}
__device__ __forceinline__ u64 fmul2(u64 a, u64 b) {
    u64 d; asm("mul.rn.f32x2 %0, %1, %2;" : "=l"(d) : "l"(a), "l"(b)); return d;
}
__device__ __forceinline__ u64 fadd2(u64 a, u64 b) {
    u64 d; asm("add.rn.f32x2 %0, %1, %2;" : "=l"(d) : "l"(a), "l"(b)); return d;
}
__device__ __forceinline__ float negf(float v) {
    return __int_as_float(__float_as_int(v) ^ 0x80000000u);
}
__device__ __forceinline__ unsigned SWZ(unsigned x) {
    return x ^ (((x >> 4) & 1u) * 5u) ^ (((x >> 5) & 1u) * 10u)
             ^ (((x >> 6) & 1u) * 1u);
}

// ---- L2 residency policies ----
__device__ __forceinline__ u64 mkpol_evict_first() {
    u64 p; asm("createpolicy.fractional.L2::evict_first.b64 %0, 1.0;" : "=l"(p));
    return p;
}
__device__ __forceinline__ u64 mkpol_evict_last() {
    u64 p; asm("createpolicy.fractional.L2::evict_last.b64 %0, 1.0;" : "=l"(p));
    return p;
}
__device__ __forceinline__ float4 ldg_stream(const float* p, u64 pol) {
    float4 v;
    asm volatile("ld.global.nc.L2::cache_hint.v4.f32 {%0,%1,%2,%3}, [%4], %5;"
                 : "=f"(v.x), "=f"(v.y), "=f"(v.z), "=f"(v.w) : "l"(p), "l"(pol));
    return v;
}
__device__ __forceinline__ uint4 ldg_consume_u4(const unsigned* p, u64 pol) {
    uint4 v;
    asm volatile("ld.global.L2::cache_hint.v4.u32 {%0,%1,%2,%3}, [%4], %5;"
                 : "=r"(v.x), "=r"(v.y), "=r"(v.z), "=r"(v.w) : "l"(p), "l"(pol));
    return v;
}
__device__ __forceinline__ void stg_keep_u4(unsigned* p, uint4 v, u64 pol) {
    asm volatile("st.global.L2::cache_hint.v4.u32 [%0], {%1,%2,%3,%4}, %5;"
                 :: "l"(p), "r"(v.x), "r"(v.y), "r"(v.z), "r"(v.w), "l"(pol)
                 : "memory");
}

// half2 <-> packed float2 (u64) helpers
__device__ __forceinline__ unsigned f2_to_h2(u64 v) {
    float lo, hi; upk2(v, lo, hi);
    __half2 h = __floats2half2_rn(lo, hi);
    return *reinterpret_cast<unsigned*>(&h);
}
__device__ __forceinline__ u64 h2_to_f2(unsigned u) {
    __half2 h = *reinterpret_cast<__half2*>(&u);
    float2 f = __half22float2(h);
    return pk2(f.x, f.y);
}

// Complex 4x4 gate on a quad; weights packed (wr,wi). Two-phase A/B form.
__device__ __forceinline__ void gate4(u64& v0, u64& v1, u64& v2, u64& v3,
                                      const u64* __restrict__ w)
{
    float r0,i0,r1,i1,r2,i2,r3,i3;
    upk2(v0,r0,i0); upk2(v1,r1,i1); upk2(v2,r2,i2); upk2(v3,r3,i3);

    u64 P0 = pk2(r0, r0), P1 = pk2(r1, r1), P2 = pk2(r2, r2), P3 = pk2(r3, r3);
    u64 A0 = fmul2(P0, w[0]);
    A0 = ffma2(P1, w[1], A0); A0 = ffma2(P2, w[2], A0); A0 = ffma2(P3, w[3], A0);
    u64 A1 = fmul2(P0, w[4]);
    A1 = ffma2(P1, w[5], A1); A1 = ffma2(P2, w[6], A1); A1 = ffma2(P3, w[7], A1);
    u64 A2 = fmul2(P0, w[8]);
    A2 = ffma2(P1, w[9], A2); A2 = ffma2(P2, w[10], A2); A2 = ffma2(P3, w[11], A2);
    u64 A3 = fmul2(P0, w[12]);
    A3 = ffma2(P1, w[13], A3); A3 = ffma2(P2, w[14], A3); A3 = ffma2(P3, w[15], A3);

    u64 Q0 = pk2(i0, i0), Q1 = pk2(i1, i1), Q2 = pk2(i2, i2), Q3 = pk2(i3, i3);
    {
        u64 B = fmul2(Q0, w[0]);
        B = ffma2(Q1, w[1], B); B = ffma2(Q2, w[2], B); B = ffma2(Q3, w[3], B);
        float bl, bh; upk2(B, bl, bh);
        v0 = fadd2(A0, pk2(negf(bh), bl));
    }
    {
        u64 B = fmul2(Q0, w[4]);
        B = ffma2(Q1, w[5], B); B = ffma2(Q2, w[6], B); B = ffma2(Q3, w[7], B);
        float bl, bh; upk2(B, bl, bh);
        v1 = fadd2(A1, pk2(negf(bh), bl));
    }
    {
        u64 B = fmul2(Q0, w[8]);
        B = ffma2(Q1, w[9], B); B = ffma2(Q2, w[10], B); B = ffma2(Q3, w[11], B);
        float bl, bh; upk2(B, bl, bh);
        v2 = fadd2(A2, pk2(negf(bh), bl));
    }
    {
        u64 B = fmul2(Q0, w[12]);
        B = ffma2(Q1, w[13], B); B = ffma2(Q2, w[14], B); B = ffma2(Q3, w[15], B);
        float bl, bh; upk2(B, bl, bh);
        v3 = fadd2(A3, pk2(negf(bh), bl));
    }
}

__device__ __forceinline__ unsigned expand4(unsigned t, int P0, int P1, int P2, int P3) {
    unsigned x = t;
    x = ((x & ~((1u << P0) - 1u)) << 1) | (x & ((1u << P0) - 1u));
    x = ((x & ~((1u << P1) - 1u)) << 1) | (x & ((1u << P1) - 1u));
    x = ((x & ~((1u << P2) - 1u)) << 1) | (x & ((1u << P2) - 1u));
    x = ((x & ~((1u << P3) - 1u)) << 1) | (x & ((1u << P3) - 1u));
    return x;
}

// Two fused gates on a 16-amp supergroup via smem round trip.
template <int P0, int P1, int P2, int P3>
__device__ __forceinline__ void apply_pair(float2* sm, unsigned tid,
                                           const float* __restrict__ gp0,
                                           const float* __restrict__ gp1)
{
    const unsigned x = expand4(tid, P0, P1, P2, P3);

    u64 p[16];
    #pragma unroll
    for (int i = 0; i < 16; ++i) {
        unsigned off = ((i & 1)        ? (1u << P0) : 0u)
                     | (((i >> 1) & 1) ? (1u << P1) : 0u)
                     | (((i >> 2) & 1) ? (1u << P2) : 0u)
                     | (((i >> 3) & 1) ? (1u << P3) : 0u);
        float2 v = sm[SWZ(x | off)];
        p[i] = pk2(v.x, v.y);
    }

    {   u64 w[16];
        #pragma unroll
        for (int k = 0; k < 16; ++k)
            w[k] = pk2(__ldg(gp0 + k), __ldg(gp0 + 16 + k));
        gate4(p[0],  p[1],  p[4],  p[5],  w);
        gate4(p[2],  p[3],  p[6],  p[7],  w);
        gate4(p[8],  p[9],  p[12], p[13], w);
        gate4(p[10], p[11], p[14], p[15], w);
    }
    {   u64 w[16];
        #pragma unroll
        for (int k = 0; k < 16; ++k)
            w[k] = pk2(__ldg(gp1 + k), __ldg(gp1 + 16 + k));
        gate4(p[0], p[2], p[8],  p[10], w);
        gate4(p[1], p[3], p[9],  p[11], w);
        gate4(p[4], p[6], p[12], p[14], w);
        gate4(p[5], p[7], p[13], p[15], w);
    }

    #pragma unroll
    for (int i = 0; i < 16; ++i) {
        unsigned off = ((i & 1)        ? (1u << P0) : 0u)
                     | (((i >> 1) & 1) ? (1u << P1) : 0u)
                     | (((i >> 2) & 1) ? (1u << P2) : 0u)
                     | (((i >> 3) & 1) ? (1u << P3) : 0u);
        float lo, hi; upk2(p[i], lo, hi);
        sm[SWZ(x | off)] = make_float2(lo, hi);
    }
}

// ---- Pass 0: gates 0..4. Tile = amp bits {0..5, 7..11}; block -> {6, 12..23} ----
__global__ __launch_bounds__(128, 5)
void qsim_pass0(const float* __restrict__ in, const float* __restrict__ gates)
{
    __shared__ float2 sm[2048];
    const unsigned t = threadIdx.x;
    const unsigned b = blockIdx.x;
    const unsigned hi = ((b & 1u) << 6) | ((b >> 1) << 12);

    // Phase 1: fused LDG (stream) + gate4 (amp 4,11 -> tile 4,10) + STS.
    {
        const u64 polF = mkpol_evict_first();
        u64 w[16];
        #pragma unroll
        for (int k = 0; k < 16; ++k)
            w[k] = pk2(__ldg(gates + 4 * 32 + k), __ldg(gates + 4 * 32 + 16 + k));

        const unsigned B = ((t & 3u) << 2) | ((t >> 2) << 5);
        u64 p[16];
        #pragma unroll
        for (int q = 0; q < 4; ++q) {
            unsigned a0 = B | ((q & 1u) << 4) | ((unsigned)(q >> 1) << 10);
            unsigned g = hi | (a0 & 63u) | ((a0 >> 6) << 7);
            float4 r4 = ldg_stream(in + g, polF);
            float4 m4 = ldg_stream(in + NSTATE + g, polF);
            p[q * 4 + 0] = pk2(r4.x, m4.x);
            p[q * 4 + 1] = pk2(r4.y, m4.y);
            p[q * 4 + 2] = pk2(r4.z, m4.z);
            p[q * 4 + 3] = pk2(r4.w, m4.w);
        }
        #pragma unroll
        for (int f = 0; f < 4; ++f)
            gate4(p[f], p[f + 4], p[f + 8], p[f + 12], w);
        #pragma unroll
        for (int i = 0; i < 16; ++i) {
            unsigned a = B | (unsigned)(i & 3)
                       | (((unsigned)(i >> 2) & 1u) << 4)
                       | (((unsigned)(i >> 3) & 1u) << 10);
            float lo, hic; upk2(p[i], lo, hic);
            sm[SWZ(a)] = make_float2(lo, hic);
        }
    }
    __syncthreads();

    // Phase 2: gates 2,3 -> tile <2,3,8,9>, smem round trip.
    apply_pair<2, 3, 8, 9>(sm, t, gates + 2 * 32, gates + 3 * 32);
    __syncthreads();

    // Phase 3: gates 0,1 -> tile <0,1,6,7>, direct half2 STG.128 pinned in L2.
    {
        const u64 polL = mkpol_evict_last();
        const unsigned x = expand4(t, 0, 1, 6, 7);
        u64 p[16];
        #pragma unroll
        for (int i = 0; i < 16; ++i) {
            unsigned off = (i & 3u) | (((i >> 2) & 1) << 6) | (((i >> 3) & 1) << 7);
            float2 v = sm[SWZ(x | off)];
            p[i] = pk2(v.x, v.y);
        }
        {   u64 w[16];
            #pragma unroll
            for (int k = 0; k < 16; ++k)
                w[k] = pk2(__ldg(gates + k), __ldg(gates + 16 + k));
            gate4(p[0],  p[1],  p[4],  p[5],  w);
            gate4(p[2],  p[3],  p[6],  p[7],  w);
            gate4(p[8],  p[9],  p[12], p[13], w);
            gate4(p[10], p[11], p[14], p[15], w);
        }
        {   u64 w[16];
            #pragma unroll
            for (int k = 0; k < 16; ++k)
                w[k] = pk2(__ldg(gates + 32 + k), __ldg(gates + 48 + k));
            gate4(p[0], p[2], p[8],  p[10], w);
            gate4(p[1], p[3], p[9],  p[11], w);
            gate4(p[4], p[6], p[12], p[14], w);
            gate4(p[5], p[7], p[13], p[15], w);
        }
        #pragma unroll
        for (int h = 0; h < 4; ++h) {
            unsigned bi = h << 2;
            unsigned a = x | ((h & 1u) << 6) | ((unsigned)(h >> 1) << 7);
            unsigned g = hi | (a & 63u) | ((a >> 6) << 7);
            uint4 u;
            u.x = f2_to_h2(p[bi + 0]);
            u.y = f2_to_h2(p[bi + 1]);
            u.z = f2_to_h2(p[bi + 2]);
            u.w = f2_to_h2(p[bi + 3]);
            stg_keep_u4(g_mid + g, u, polL);
        }
    }
}

// ---- Pass 1: gates 5..7. Tile = amp bits {0..7, 12..14}; block -> {8..11, 15..23} ----
__global__ __launch_bounds__(128, 5)
void qsim_pass1(float* __restrict__ st, const float* __restrict__ gates)
{
    __shared__ float2 sm[2048];
    const unsigned t = threadIdx.x;
    const unsigned b = blockIdx.x;
    const unsigned hi = ((b & 15u) << 8) | ((b >> 4) << 15);

    // Phase 1: fused half2 LDG (consume from L2) + gate7 (amp 7,14 -> tile 7,10) + STS.
    {
        const u64 polF = mkpol_evict_first();
        u64 w[16];
        #pragma unroll
        for (int k = 0; k < 16; ++k)
            w[k] = pk2(__ldg(gates + 7 * 32 + k), __ldg(gates + 7 * 32 + 16 + k));

        const unsigned B = ((t & 31u) << 2) | (((t >> 5) & 3u) << 8);
        u64 p[16];
        #pragma unroll
        for (int q = 0; q < 4; ++q) {
            unsigned a0 = B | ((q & 1u) << 7) | ((unsigned)(q >> 1) << 10);
            unsigned g = hi | (a0 & 255u) | ((a0 >> 8) << 12);
            uint4 u = ldg_consume_u4(g_mid + g, polF);
            p[q * 4 + 0] = h2_to_f2(u.x);
            p[q * 4 + 1] = h2_to_f2(u.y);
            p[q * 4 + 2] = h2_to_f2(u.z);
            p[q * 4 + 3] = h2_to_f2(u.w);
        }
        #pragma unroll
        for (int f = 0; f < 4; ++f)
            gate4(p[f], p[f + 4], p[f + 8], p[f + 12], w);
        #pragma unroll
        for (int i = 0; i < 16; ++i) {
            unsigned a = B | (unsigned)(i & 3)
                       | (((unsigned)(i >> 2) & 1u) << 7)
                       | (((unsigned)(i >> 3) & 1u) << 10);
            float lo, hic; upk2(p[i], lo, hic);
            sm[SWZ(a)] = make_float2(lo, hic);
        }
    }
    __syncthreads();

    // Phase 2: gates 5,6 -> tile <5,6,8,9>, LDS + direct STG.32 (128B-coalesced).
    {
        const unsigned x = expand4(t, 5, 6, 8, 9);
        u64 p[16];
        #pragma unroll
        for (int i = 0; i < 16; ++i) {
            unsigned off = ((i & 1u) << 5) | (((i >> 1) & 1u) << 6)
                         | (((i >> 2) & 1u) << 8) | (((i >> 3) & 1u) << 9);
            float2 v = sm[SWZ(x | off)];
            p[i] = pk2(v.x, v.y);
        }
        {   u64 w[16];
            #pragma unroll
            for (int k = 0; k < 16; ++k)
                w[k] = pk2(__ldg(gates + 5 * 32 + k), __ldg(gates + 5 * 32 + 16 + k));
            gate4(p[0],  p[1],  p[4],  p[5],  w);
            gate4(p[2],  p[3],  p[6],  p[7],  w);
            gate4(p[8],  p[9],  p[12], p[13], w);
            gate4(p[10], p[11], p[14], p[15], w);
        }
        {   u64 w[16];
            #pragma unroll
            for (int k = 0; k < 16; ++k)
                w[k] = pk2(__ldg(gates + 6 * 32 + k), __ldg(gates + 6 * 32 + 16 + k));
            gate4(p[0], p[2], p[8],  p[10], w);
            gate4(p[1], p[3], p[9],  p[11], w);
            gate4(p[4], p[6], p[12], p[14], w);
            gate4(p[5], p[7], p[13], p[15], w);
        }
        #pragma unroll
        for (int i = 0; i < 16; ++i) {
            unsigned off = ((i & 1u) << 5) | (((i >> 1) & 1u) << 6)
                         | (((i >> 2) & 1u) << 8) | (((i >> 3) & 1u) << 9);
            unsigned a = x | off;
            unsigned g = hi | (a & 255u) | ((a >> 8) << 12);
            float lo, hic; upk2(p[i], lo, hic);
            st[g] = lo;
            st[NSTATE + g] = hic;
        }
    }
}

extern "C" void kernel_launch(void* const* d_in, const int* in_sizes, int n_in,
                              void* d_out, int out_size)
{
    const float* state = (const float*)d_in[0];   // 2 * 2^24 floats (re, im planes)
    const float* gates = (const float*)d_in[1];   // 8 * 2 * 4 * 4 floats
    float* out = (float*)d_out;

    qsim_pass0<<<8192, 128>>>(state, gates);   // gates 0..4 -> fp16 scratch
    qsim_pass1<<<8192, 128>>>(out, gates);     // gates 5..7 -> fp32 output
}